// round 1
// baseline (speedup 1.0000x reference)
#include <cuda_runtime.h>
#include <math.h>

#define Bsz 64
#define TIN 128
#define TOUT 32
#define Vv 32000
#define Ee 512
#define Hh 1024
#define Aa 512
#define Ll 4

// ---------------- scratch (static device memory; no allocations) ----------------
__device__ float g_encproj[TIN * Bsz * Aa];      // (T,B,A) 16.8MB
__device__ float g_dec[Bsz * Aa];                // (B,A)
__device__ float g_scores[TIN * Bsz];            // (T,B)
__device__ float g_x0[Bsz * (2 * Hh + Ee)];      // [context | emb]
__device__ float g_xl[Bsz * 3 * Hh];             // [out | context]
__device__ float g_h[Ll * Bsz * Hh];
__device__ float g_c[Ll * Bsz * Hh];
__device__ float g_out[Bsz * Hh];
__device__ float g_gates[Bsz * 4 * Hh];
__device__ float g_logits[(size_t)Bsz * Vv];     // 8.2MB
__device__ int   g_tok[Bsz];

// ---------------- init ----------------
__global__ void init_state_kernel(const float* __restrict__ h0,
                                  const float* __restrict__ c0,
                                  const float* __restrict__ o0,
                                  const int* __restrict__ eos)
{
    int idx = blockIdx.x * blockDim.x + threadIdx.x;
    if (idx < Ll * Bsz * Hh) { g_h[idx] = h0[idx]; g_c[idx] = c0[idx]; }
    if (idx < Bsz * Hh) g_out[idx] = o0[idx];
    if (idx < Bsz) g_tok[idx] = eos[0];
}

// ---------------- generic fp32 GEMM: C[M,N] = A[M,K] @ B[K,N] (+bias)(+C)(relu) ----
// Block tile 64x128, 256 threads, per-thread 4x8. Requires M%64==0, N%128==0, K%16==0.
template <int ACT, int ACCUM>
__global__ __launch_bounds__(256) void gemm_kernel(
    const float* __restrict__ A, const float* __restrict__ Bm,
    const float* __restrict__ bias, float* __restrict__ C,
    int M, int N, int K)
{
    __shared__ float sA[16][64];
    __shared__ float sB[16][128];
    const int tid = threadIdx.x;
    const int bn0 = blockIdx.x * 128;
    const int bm0 = blockIdx.y * 64;
    const int tr = tid >> 4, tc = tid & 15;
    const int m0 = tr * 4, n0 = tc * 8;
    const int arow = tid >> 2, akq = (tid & 3) << 2;
    const int bkr = tid >> 5, bnq = (tid & 31) << 2;
    const float* Aptr = A + (size_t)(bm0 + arow) * K + akq;
    const float* Bptr = Bm + (size_t)bkr * N + bn0 + bnq;

    float acc[4][8];
#pragma unroll
    for (int i = 0; i < 4; i++)
#pragma unroll
        for (int j = 0; j < 8; j++) acc[i][j] = 0.f;

    for (int k0 = 0; k0 < K; k0 += 16) {
        float4 av = *(const float4*)(Aptr + k0);
        float4 bv0 = *(const float4*)(Bptr + (size_t)k0 * N);
        float4 bv1 = *(const float4*)(Bptr + (size_t)(k0 + 8) * N);
        sA[akq + 0][arow] = av.x;
        sA[akq + 1][arow] = av.y;
        sA[akq + 2][arow] = av.z;
        sA[akq + 3][arow] = av.w;
        *(float4*)&sB[bkr][bnq] = bv0;
        *(float4*)&sB[bkr + 8][bnq] = bv1;
        __syncthreads();
#pragma unroll
        for (int kk = 0; kk < 16; kk++) {
            float4 a4  = *(const float4*)&sA[kk][m0];
            float4 b40 = *(const float4*)&sB[kk][n0];
            float4 b41 = *(const float4*)&sB[kk][n0 + 4];
            float a[4] = {a4.x, a4.y, a4.z, a4.w};
            float b[8] = {b40.x, b40.y, b40.z, b40.w, b41.x, b41.y, b41.z, b41.w};
#pragma unroll
            for (int i = 0; i < 4; i++)
#pragma unroll
                for (int j = 0; j < 8; j++)
                    acc[i][j] = fmaf(a[i], b[j], acc[i][j]);
        }
        __syncthreads();
    }

#pragma unroll
    for (int i = 0; i < 4; i++) {
        float* Crow = C + (size_t)(bm0 + m0 + i) * N + bn0 + n0;
#pragma unroll
        for (int j = 0; j < 8; j++) {
            float v = acc[i][j];
            if (bias) v += bias[bn0 + n0 + j];
            if (ACCUM) v += Crow[j];
            if (ACT) v = fmaxf(v, 0.f);
            Crow[j] = v;
        }
    }
}

// ---------------- attention scores: s[t,b] = sum_a tanh(enc_proj+dec)*A2 + b2 + mask
__global__ __launch_bounds__(256) void attn_scores_kernel(
    const float* __restrict__ is_on,
    const float* __restrict__ A2, const float* __restrict__ b2)
{
    const int t = blockIdx.x, b = blockIdx.y;
    const float* ep = g_encproj + ((size_t)t * Bsz + b) * Aa;
    const float* dp = g_dec + b * Aa;
    const int tid = threadIdx.x;
    float s = 0.f;
#pragma unroll
    for (int a = tid; a < Aa; a += 256)
        s += tanhf(ep[a] + dp[a]) * A2[a];
    __shared__ float red[256];
    red[tid] = s;
    __syncthreads();
    for (int st = 128; st > 0; st >>= 1) {
        if (tid < st) red[tid] += red[tid + st];
        __syncthreads();
    }
    if (tid == 0)
        g_scores[t * Bsz + b] = red[0] + b2[0] + (1.f - is_on[t * Bsz + b]) * (-1e30f);
}

// ---------------- softmax over T + context = sum_t alpha*enc ----------------
__global__ __launch_bounds__(256) void attn_context_kernel(const float* __restrict__ enc)
{
    const int b = blockIdx.x;
    const int dchunk = blockIdx.y;  // 8 chunks of 256 over 2H
    const int tid = threadIdx.x;
    __shared__ float sAlpha[TIN];
    __shared__ float red[256];

    float v = (tid < TIN) ? g_scores[tid * Bsz + b] : -3.4e38f;
    red[tid] = v;
    __syncthreads();
    for (int st = 128; st > 0; st >>= 1) {
        if (tid < st) red[tid] = fmaxf(red[tid], red[tid + st]);
        __syncthreads();
    }
    float mx = red[0];
    __syncthreads();
    float e = (tid < TIN) ? expf(v - mx) : 0.f;
    if (tid < TIN) sAlpha[tid] = e;
    red[tid] = e;
    __syncthreads();
    for (int st = 128; st > 0; st >>= 1) {
        if (tid < st) red[tid] += red[tid + st];
        __syncthreads();
    }
    float inv = 1.f / red[0];

    const int d = dchunk * 256 + tid;
    const float* ep = enc + (size_t)b * (2 * Hh) + d;
    float acc = 0.f;
#pragma unroll 4
    for (int t = 0; t < TIN; t++)
        acc += sAlpha[t] * ep[(size_t)t * Bsz * 2 * Hh];
    float ctx = acc * inv;
    g_x0[b * (2 * Hh + Ee) + d] = ctx;
    g_xl[b * 3 * Hh + Hh + d] = ctx;
}

// ---------------- embedding gather (prev token feedback) ----------------
__global__ void gather_emb_kernel(const float* __restrict__ emb)
{
    const int b = blockIdx.x;
    const int e = blockIdx.y * 256 + threadIdx.x;
    g_x0[b * (2 * Hh + Ee) + 2 * Hh + e] = emb[(size_t)g_tok[b] * Ee + e];
}

// ---------------- LSTM pointwise ----------------
__device__ __forceinline__ float sigmoidf_(float x) { return 1.f / (1.f + expf(-x)); }

__global__ void lstm_cell_kernel(int layer, int last)
{
    const int idx = blockIdx.x * blockDim.x + threadIdx.x;  // B*H
    const int b = idx >> 10, j = idx & (Hh - 1);
    const float* g = g_gates + b * 4 * Hh;
    float i  = sigmoidf_(g[j]);
    float f  = sigmoidf_(g[Hh + j]);
    float gg = tanhf(g[2 * Hh + j]);
    float o  = sigmoidf_(g[3 * Hh + j]);
    float* cp = g_c + (size_t)layer * Bsz * Hh;
    float* hp = g_h + (size_t)layer * Bsz * Hh;
    float cn = f * cp[idx] + i * gg;
    float hn = o * tanhf(cn);
    cp[idx] = cn;
    hp[idx] = hn;
    if (last) {
        g_out[idx] = hn;
        g_xl[b * 3 * Hh + j] = hn;
    }
}

// ---------------- softmax over V + greedy argmax ----------------
__global__ __launch_bounds__(1024) void softmax_v_kernel(float* __restrict__ probs)
{
    const int b = blockIdx.x;
    const float* lr = g_logits + (size_t)b * Vv;
    const int tid = threadIdx.x;
    __shared__ float rv[1024];
    __shared__ int ri[1024];

    float m = -3.4e38f;
    int mi = 0;
    for (int i = tid; i < Vv; i += 1024) {
        float x = lr[i];
        if (x > m) { m = x; mi = i; }
    }
    rv[tid] = m; ri[tid] = mi;
    __syncthreads();
    for (int st = 512; st > 0; st >>= 1) {
        if (tid < st) {
            float vo = rv[tid + st]; int io = ri[tid + st];
            if (vo > rv[tid] || (vo == rv[tid] && io < ri[tid])) { rv[tid] = vo; ri[tid] = io; }
        }
        __syncthreads();
    }
    float mx = rv[0];
    if (tid == 0) g_tok[b] = ri[0];
    __syncthreads();

    float s = 0.f;
    for (int i = tid; i < Vv; i += 1024) s += expf(lr[i] - mx);
    rv[tid] = s;
    __syncthreads();
    for (int st = 512; st > 0; st >>= 1) {
        if (tid < st) rv[tid] += rv[tid + st];
        __syncthreads();
    }
    float inv = 1.f / rv[0];
    float* pr = probs + (size_t)b * Vv;
    for (int i = tid; i < Vv; i += 1024) pr[i] = expf(lr[i] - mx) * inv;
}

// ---------------- host orchestration (graph-capturable) ----------------
extern "C" void kernel_launch(void* const* d_in, const int* in_sizes, int n_in,
                              void* d_out, int out_size)
{
    const float* enc   = (const float*)d_in[0];   // (T,B,2H)
    const float* is_on = (const float*)d_in[1];   // (T,B)
    const float* emb   = (const float*)d_in[2];   // (V,E)
    const float* A1    = (const float*)d_in[3];   // (3H,A)
    const float* b1    = (const float*)d_in[4];
    const float* A2    = (const float*)d_in[5];   // (A,1)
    const float* b2    = (const float*)d_in[6];
    const float* W_ih0 = (const float*)d_in[7];   // (2H+E,4H)
    const float* W_ihr = (const float*)d_in[8];   // (L-1,H,4H)
    const float* W_hh  = (const float*)d_in[9];   // (L,H,4H)
    const float* b_ih  = (const float*)d_in[10];  // (L,4H)
    const float* b_hh  = (const float*)d_in[11];
    const float* Wl    = (const float*)d_in[12];  // (3H,V)
    const float* bl    = (const float*)d_in[13];
    const float* h0    = (const float*)d_in[14];
    const float* c0    = (const float*)d_in[15];
    const float* o0    = (const float*)d_in[16];
    const int*   eos   = (const int*)d_in[17];
    float* out = (float*)d_out;

    float *p_encproj, *p_dec, *p_x0, *p_xl, *p_h, *p_gates, *p_logits, *p_out;
    cudaGetSymbolAddress((void**)&p_encproj, g_encproj);
    cudaGetSymbolAddress((void**)&p_dec, g_dec);
    cudaGetSymbolAddress((void**)&p_x0, g_x0);
    cudaGetSymbolAddress((void**)&p_xl, g_xl);
    cudaGetSymbolAddress((void**)&p_h, g_h);
    cudaGetSymbolAddress((void**)&p_gates, g_gates);
    cudaGetSymbolAddress((void**)&p_logits, g_logits);
    cudaGetSymbolAddress((void**)&p_out, g_out);

    // state init
    init_state_kernel<<<(Ll * Bsz * Hh + 255) / 256, 256>>>(h0, c0, o0, eos);

    // enc_proj = enc(8192,2048) @ A1[H:](2048,512)  (once)
    gemm_kernel<0, 0><<<dim3(Aa / 128, (TIN * Bsz) / 64), 256>>>(
        enc, A1 + (size_t)Hh * Aa, nullptr, p_encproj, TIN * Bsz, Aa, 2 * Hh);

    for (int s = 0; s < TOUT; s++) {
        // dec = out_prev @ A1[:H] + b1   (64,512,K=1024)
        gemm_kernel<0, 0><<<dim3(Aa / 128, 1), 256>>>(p_out, A1, b1, p_dec, Bsz, Aa, Hh);
        attn_scores_kernel<<<dim3(TIN, Bsz), 256>>>(is_on, A2, b2);
        attn_context_kernel<<<dim3(Bsz, (2 * Hh) / 256), 256>>>(enc);
        gather_emb_kernel<<<dim3(Bsz, Ee / 256), 256>>>(emb);

        for (int l = 0; l < Ll; l++) {
            const float* x = (l == 0) ? p_x0 : (p_h + (size_t)(l - 1) * Bsz * Hh);
            int Kx = (l == 0) ? (2 * Hh + Ee) : Hh;
            const float* Wih = (l == 0) ? W_ih0 : (W_ihr + (size_t)(l - 1) * Hh * 4 * Hh);
            gemm_kernel<0, 0><<<dim3(4 * Hh / 128, 1), 256>>>(
                x, Wih, b_ih + (size_t)l * 4 * Hh, p_gates, Bsz, 4 * Hh, Kx);
            gemm_kernel<0, 1><<<dim3(4 * Hh / 128, 1), 256>>>(
                p_h + (size_t)l * Bsz * Hh, W_hh + (size_t)l * Hh * 4 * Hh,
                b_hh + (size_t)l * 4 * Hh, p_gates, Bsz, 4 * Hh, Hh);
            lstm_cell_kernel<<<(Bsz * Hh) / 256, 256>>>(l, l == Ll - 1 ? 1 : 0);
        }

        // logits = relu([out|context] @ Wl + bl)   (64,32000,K=3072)
        gemm_kernel<1, 0><<<dim3(Vv / 128, 1), 256>>>(p_xl, Wl, bl, p_logits, Bsz, Vv, 3 * Hh);

        softmax_v_kernel<<<Bsz, 1024>>>(out + (size_t)s * Bsz * Vv);
    }
    (void)in_sizes; (void)n_in; (void)out_size;
}

// round 2
// speedup vs baseline: 3.2703x; 3.2703x over previous
#include <cuda_runtime.h>
#include <math.h>
#include <stdint.h>

#define Bsz 64
#define TIN 128
#define TOUT 32
#define Vv 32000
#define Ee 512
#define Hh 1024
#define Aa 512
#define Ll 4

// ---------------- scratch (static device memory; no allocations) ----------------
__device__ __align__(16) float g_encproj[TIN * Bsz * Aa];
__device__ __align__(16) float g_dec[Bsz * Aa];
__device__ __align__(16) float g_scores[TIN * Bsz];
__device__ __align__(16) float g_x0[Bsz * (2 * Hh + Ee)];
__device__ __align__(16) float g_xl[Bsz * 3 * Hh];
__device__ __align__(16) float g_ha[Ll * Bsz * Hh];
__device__ __align__(16) float g_hb[Ll * Bsz * Hh];
__device__ __align__(16) float g_c[Ll * Bsz * Hh];
__device__ __align__(16) float g_out[Bsz * Hh];
__device__ __align__(16) float g_logits[(size_t)Bsz * Vv];
__device__ int g_tok[Bsz];

// ---------------- init ----------------
__global__ void init_state_kernel(const float* __restrict__ h0,
                                  const float* __restrict__ c0,
                                  const float* __restrict__ o0,
                                  const int* __restrict__ eos)
{
    int idx = blockIdx.x * blockDim.x + threadIdx.x;
    if (idx < Ll * Bsz * Hh) { g_ha[idx] = h0[idx]; g_c[idx] = c0[idx]; }
    if (idx < Bsz * Hh) g_out[idx] = o0[idx];
    if (idx < Bsz) g_tok[idx] = eos[0];
}

// ---------------- tf32 helpers ----------------
__device__ __forceinline__ uint32_t f2tf(float x)
{
    uint32_t u;
    asm("cvt.rna.tf32.f32 %0, %1;" : "=r"(u) : "f"(x));
    return u;
}

__device__ __forceinline__ void mma_tf32(float* c, const uint32_t* a, const uint32_t* b)
{
    asm volatile(
        "mma.sync.aligned.m16n8k8.row.col.f32.tf32.tf32.f32 "
        "{%0,%1,%2,%3}, {%4,%5,%6,%7}, {%8,%9}, {%0,%1,%2,%3};"
        : "+f"(c[0]), "+f"(c[1]), "+f"(c[2]), "+f"(c[3])
        : "r"(a[0]), "r"(a[1]), "r"(a[2]), "r"(a[3]), "r"(b[0]), "r"(b[1]));
}

__device__ __forceinline__ float sigmoidf_(float x) { return 1.f / (1.f + expf(-x)); }

// ---------------- tf32 MMA GEMM ----------------
// C[64 x 128-tile] = [A0 | A1] @ [B0 ; B1]  (segmented K), M block = 64 rows.
// 256 threads = 8 warps arranged 2(M) x 4(N). Warp: 32 rows x 32 cols.
// MODE 0: C = A@B (+bias). MODE 1: relu(A@B + bias). MODE 2: fused LSTM cell.
// GATED=1: B columns interleave the 4 LSTM gates at 8-col granularity so each
// warp's 4 n-tiles are gates i,f,g,o of the same hidden indices.
template <int MODE, int GATED>
__global__ __launch_bounds__(256) void mma_gemm_kernel(
    const float* __restrict__ A0, int lda0, const float* __restrict__ B0, int K0,
    const float* __restrict__ A1p, int lda1, const float* __restrict__ B1p, int K1,
    int ldb,
    const float* __restrict__ bias, const float* __restrict__ bias2,
    float* __restrict__ C, int ldc,
    float* __restrict__ cell, float* __restrict__ hout, int last)
{
    __shared__ uint32_t sA[64 * 36];   // [m][k] stride 36 (pad 4)
    __shared__ uint32_t sB[4096];      // 4 ksteps x (krow*128 + nin*16 + (nouter^swz))

    const int tid = threadIdx.x;
    const int lane = tid & 31;
    const int wid = tid >> 5;
    const int warpM = wid >> 2;     // 0..1
    const int warpN = wid & 3;      // 0..3
    const int M0 = blockIdx.y * 64;

    // global A load coords: 2 rows of float4 per thread
    const int am = tid >> 3;            // 0..31
    const int ak = (tid & 7) << 2;      // 0,4,...,28
    // global B load col (constant per thread)
    const int bn = lane << 2;           // 0..124
    int bcol;
    if (GATED)
        bcol = ((bn >> 3) & 3) * Hh + blockIdx.x * 32 + ((bn >> 5) << 3) + (bn & 7);
    else
        bcol = blockIdx.x * 128 + bn;

    const int nch0 = K0 >> 5;
    const int nch1 = K1 >> 5;
    const int ntot = nch0 + nch1;

    float4 rA0, rA1, rB[4];

    auto load_global = [&](int c) {
        const float* Ap;
        const float* Bp;
        int lda, k0;
        if (c < nch0) { Ap = A0; lda = lda0; Bp = B0; k0 = c << 5; }
        else { Ap = A1p; lda = lda1; Bp = B1p; k0 = (c - nch0) << 5; }
        rA0 = *(const float4*)(Ap + (size_t)(M0 + am) * lda + k0 + ak);
        rA1 = *(const float4*)(Ap + (size_t)(M0 + am + 32) * lda + k0 + ak);
#pragma unroll
        for (int r = 0; r < 4; r++)
            rB[r] = *(const float4*)(Bp + (size_t)(k0 + r * 8 + wid) * ldb + bcol);
    };

    float acc[2][4][4];
#pragma unroll
    for (int mt = 0; mt < 2; mt++)
#pragma unroll
        for (int t = 0; t < 4; t++)
#pragma unroll
            for (int j = 0; j < 4; j++) acc[mt][t][j] = 0.f;

    load_global(0);

    const int nin0 = (lane & 1) * 4;
    const int nout = lane >> 1;

    for (int c = 0; c < ntot; c++) {
        __syncthreads();
        // store A (tf32)
        {
            uint4 v0 = make_uint4(f2tf(rA0.x), f2tf(rA0.y), f2tf(rA0.z), f2tf(rA0.w));
            uint4 v1 = make_uint4(f2tf(rA1.x), f2tf(rA1.y), f2tf(rA1.z), f2tf(rA1.w));
            *(uint4*)&sA[am * 36 + ak] = v0;
            *(uint4*)&sA[(am + 32) * 36 + ak] = v1;
        }
        // store B (tf32, swizzled)
#pragma unroll
        for (int r = 0; r < 4; r++) {
            int base = r * 1024 + wid * 128;
            int sw = (wid & 3) * 4;
            sB[base + (nin0 + 0) * 16 + (nout ^ sw)] = f2tf(rB[r].x);
            sB[base + (nin0 + 1) * 16 + (nout ^ sw)] = f2tf(rB[r].y);
            sB[base + (nin0 + 2) * 16 + (nout ^ sw)] = f2tf(rB[r].z);
            sB[base + (nin0 + 3) * 16 + (nout ^ sw)] = f2tf(rB[r].w);
        }
        __syncthreads();
        if (c + 1 < ntot) load_global(c + 1);

#pragma unroll
        for (int ks = 0; ks < 4; ks++) {
            uint32_t a[2][4];
#pragma unroll
            for (int mt = 0; mt < 2; mt++) {
                int mrow = warpM * 32 + mt * 16 + (lane >> 2);
                const uint32_t* pa = &sA[mrow * 36 + ks * 8 + (lane & 3)];
                a[mt][0] = pa[0];
                a[mt][1] = pa[8 * 36];
                a[mt][2] = pa[4];
                a[mt][3] = pa[8 * 36 + 4];
            }
            int bbase = ks * 1024 + (lane & 3) * 128 + (lane >> 2) * 16 +
                        ((warpN * 4) ^ ((lane & 3) * 4));
            uint4 b0 = *(const uint4*)&sB[bbase];
            uint4 b1 = *(const uint4*)&sB[bbase + 512];
            uint32_t bb[4][2] = {{b0.x, b1.x}, {b0.y, b1.y}, {b0.z, b1.z}, {b0.w, b1.w}};
#pragma unroll
            for (int mt = 0; mt < 2; mt++)
#pragma unroll
                for (int t = 0; t < 4; t++)
                    mma_tf32(acc[mt][t], a[mt], bb[t]);
        }
    }

    // ------------- epilogue -------------
    if (MODE == 2) {
#pragma unroll
        for (int j = 0; j < 4; j++) {
            int idx = blockIdx.x * 32 + warpN * 8 + (lane & 3) * 2 + (j & 1);
            float bi = bias[idx] + bias2[idx];
            float bf = bias[Hh + idx] + bias2[Hh + idx];
            float bg = bias[2 * Hh + idx] + bias2[2 * Hh + idx];
            float bo = bias[3 * Hh + idx] + bias2[3 * Hh + idx];
#pragma unroll
            for (int mt = 0; mt < 2; mt++) {
                int row = warpM * 32 + mt * 16 + (lane >> 2) + ((j & 2) << 2);
                float iv = sigmoidf_(acc[mt][0][j] + bi);
                float fv = sigmoidf_(acc[mt][1][j] + bf);
                float gv = tanhf(acc[mt][2][j] + bg);
                float ov = sigmoidf_(acc[mt][3][j] + bo);
                size_t off = (size_t)row * Hh + idx;
                float cn = fv * cell[off] + iv * gv;
                float hn = ov * tanhf(cn);
                cell[off] = cn;
                hout[off] = hn;
                if (last) {
                    g_out[off] = hn;
                    g_xl[(size_t)row * 3 * Hh + idx] = hn;
                }
            }
        }
    } else {
#pragma unroll
        for (int mt = 0; mt < 2; mt++)
#pragma unroll
            for (int t = 0; t < 4; t++)
#pragma unroll
                for (int j = 0; j < 4; j++) {
                    int row = M0 + warpM * 32 + mt * 16 + (lane >> 2) + ((j & 2) << 2);
                    int col = blockIdx.x * 128 + warpN * 32 + t * 8 + (lane & 3) * 2 + (j & 1);
                    float v = acc[mt][t][j];
                    if (bias) v += bias[col];
                    if (MODE == 1) v = fmaxf(v, 0.f);
                    C[(size_t)row * ldc + col] = v;
                }
    }
}

// ---------------- attention scores ----------------
__global__ __launch_bounds__(256) void attn_scores_kernel(
    const float* __restrict__ is_on,
    const float* __restrict__ A2, const float* __restrict__ b2)
{
    const int t = blockIdx.x, b = blockIdx.y;
    const float* ep = g_encproj + ((size_t)t * Bsz + b) * Aa;
    const float* dp = g_dec + b * Aa;
    const int tid = threadIdx.x;
    float s = 0.f;
#pragma unroll
    for (int a = tid; a < Aa; a += 256)
        s += tanhf(ep[a] + dp[a]) * A2[a];
    __shared__ float red[256];
    red[tid] = s;
    __syncthreads();
    for (int st = 128; st > 0; st >>= 1) {
        if (tid < st) red[tid] += red[tid + st];
        __syncthreads();
    }
    if (tid == 0)
        g_scores[t * Bsz + b] = red[0] + b2[0] + (1.f - is_on[t * Bsz + b]) * (-1e30f);
}

// ---------------- softmax over T + context ----------------
__global__ __launch_bounds__(256) void attn_context_kernel(const float* __restrict__ enc)
{
    const int b = blockIdx.x;
    const int dchunk = blockIdx.y;
    const int tid = threadIdx.x;
    __shared__ float sAlpha[TIN];
    __shared__ float red[256];

    float v = (tid < TIN) ? g_scores[tid * Bsz + b] : -3.4e38f;
    red[tid] = v;
    __syncthreads();
    for (int st = 128; st > 0; st >>= 1) {
        if (tid < st) red[tid] = fmaxf(red[tid], red[tid + st]);
        __syncthreads();
    }
    float mx = red[0];
    __syncthreads();
    float e = (tid < TIN) ? expf(v - mx) : 0.f;
    if (tid < TIN) sAlpha[tid] = e;
    red[tid] = e;
    __syncthreads();
    for (int st = 128; st > 0; st >>= 1) {
        if (tid < st) red[tid] += red[tid + st];
        __syncthreads();
    }
    float inv = 1.f / red[0];

    const int d = dchunk * 256 + tid;
    const float* ep = enc + (size_t)b * (2 * Hh) + d;
    float acc = 0.f;
#pragma unroll 4
    for (int t = 0; t < TIN; t++)
        acc += sAlpha[t] * ep[(size_t)t * Bsz * 2 * Hh];
    float ctx = acc * inv;
    g_x0[b * (2 * Hh + Ee) + d] = ctx;
    g_xl[b * 3 * Hh + Hh + d] = ctx;
}

// ---------------- embedding gather ----------------
__global__ void gather_emb_kernel(const float* __restrict__ emb)
{
    const int b = blockIdx.x;
    const int e = blockIdx.y * 256 + threadIdx.x;
    g_x0[b * (2 * Hh + Ee) + 2 * Hh + e] = emb[(size_t)g_tok[b] * Ee + e];
}

// ---------------- softmax over V + argmax ----------------
__global__ __launch_bounds__(1024) void softmax_v_kernel(float* __restrict__ probs)
{
    const int b = blockIdx.x;
    const float* lr = g_logits + (size_t)b * Vv;
    const int tid = threadIdx.x;
    __shared__ float rv[1024];
    __shared__ int ri[1024];

    float m = -3.4e38f;
    int mi = 0;
    for (int i = tid; i < Vv; i += 1024) {
        float x = lr[i];
        if (x > m) { m = x; mi = i; }
    }
    rv[tid] = m; ri[tid] = mi;
    __syncthreads();
    for (int st = 512; st > 0; st >>= 1) {
        if (tid < st) {
            float vo = rv[tid + st]; int io = ri[tid + st];
            if (vo > rv[tid] || (vo == rv[tid] && io < ri[tid])) { rv[tid] = vo; ri[tid] = io; }
        }
        __syncthreads();
    }
    float mx = rv[0];
    if (tid == 0) g_tok[b] = ri[0];
    __syncthreads();

    float s = 0.f;
    for (int i = tid; i < Vv; i += 1024) s += expf(lr[i] - mx);
    rv[tid] = s;
    __syncthreads();
    for (int st = 512; st > 0; st >>= 1) {
        if (tid < st) rv[tid] += rv[tid + st];
        __syncthreads();
    }
    float inv = 1.f / rv[0];
    float* pr = probs + (size_t)b * Vv;
    for (int i = tid; i < Vv; i += 1024) pr[i] = expf(lr[i] - mx) * inv;
}

// ---------------- host orchestration ----------------
extern "C" void kernel_launch(void* const* d_in, const int* in_sizes, int n_in,
                              void* d_out, int out_size)
{
    const float* enc   = (const float*)d_in[0];
    const float* is_on = (const float*)d_in[1];
    const float* emb   = (const float*)d_in[2];
    const float* A1    = (const float*)d_in[3];
    const float* b1    = (const float*)d_in[4];
    const float* A2    = (const float*)d_in[5];
    const float* b2    = (const float*)d_in[6];
    const float* W_ih0 = (const float*)d_in[7];
    const float* W_ihr = (const float*)d_in[8];
    const float* W_hh  = (const float*)d_in[9];
    const float* b_ih  = (const float*)d_in[10];
    const float* b_hh  = (const float*)d_in[11];
    const float* Wl    = (const float*)d_in[12];
    const float* bl    = (const float*)d_in[13];
    const float* h0    = (const float*)d_in[14];
    const float* c0    = (const float*)d_in[15];
    const float* o0    = (const float*)d_in[16];
    const int*   eos   = (const int*)d_in[17];
    float* out = (float*)d_out;

    float *p_encproj, *p_dec, *p_x0, *p_xl, *p_ha, *p_hb, *p_c, *p_out, *p_logits;
    cudaGetSymbolAddress((void**)&p_encproj, g_encproj);
    cudaGetSymbolAddress((void**)&p_dec, g_dec);
    cudaGetSymbolAddress((void**)&p_x0, g_x0);
    cudaGetSymbolAddress((void**)&p_xl, g_xl);
    cudaGetSymbolAddress((void**)&p_ha, g_ha);
    cudaGetSymbolAddress((void**)&p_hb, g_hb);
    cudaGetSymbolAddress((void**)&p_c, g_c);
    cudaGetSymbolAddress((void**)&p_out, g_out);
    cudaGetSymbolAddress((void**)&p_logits, g_logits);

    init_state_kernel<<<(Ll * Bsz * Hh + 255) / 256, 256>>>(h0, c0, o0, eos);

    // enc_proj = enc @ A1[H:]   (8192 x 512, K=2048)
    mma_gemm_kernel<0, 0><<<dim3(4, 128), 256>>>(
        enc, 2 * Hh, A1 + (size_t)Hh * Aa, 2 * Hh,
        nullptr, 0, nullptr, 0, Aa,
        nullptr, nullptr, p_encproj, Aa, nullptr, nullptr, 0);

    for (int s = 0; s < TOUT; s++) {
        float* hold = (s & 1) ? p_hb : p_ha;
        float* hnew = (s & 1) ? p_ha : p_hb;

        // dec = out_prev @ A1[:H] + b1
        mma_gemm_kernel<0, 0><<<dim3(4, 1), 256>>>(
            p_out, Hh, A1, Hh, nullptr, 0, nullptr, 0, Aa,
            b1, nullptr, p_dec, Aa, nullptr, nullptr, 0);

        attn_scores_kernel<<<dim3(TIN, Bsz), 256>>>(is_on, A2, b2);
        attn_context_kernel<<<dim3(Bsz, (2 * Hh) / 256), 256>>>(enc);
        gather_emb_kernel<<<dim3(Bsz, Ee / 256), 256>>>(emb);

        for (int l = 0; l < Ll; l++) {
            const float* x = (l == 0) ? p_x0 : (hnew + (size_t)(l - 1) * Bsz * Hh);
            int Kx = (l == 0) ? (2 * Hh + Ee) : Hh;
            const float* Wih = (l == 0) ? W_ih0 : (W_ihr + (size_t)(l - 1) * Hh * 4 * Hh);
            mma_gemm_kernel<2, 1><<<dim3(32, 1), 256>>>(
                x, Kx, Wih, Kx,
                hold + (size_t)l * Bsz * Hh, Hh, W_hh + (size_t)l * Hh * 4 * Hh, Hh,
                4 * Hh,
                b_ih + (size_t)l * 4 * Hh, b_hh + (size_t)l * 4 * Hh,
                nullptr, 0,
                p_c + (size_t)l * Bsz * Hh, hnew + (size_t)l * Bsz * Hh,
                (l == Ll - 1) ? 1 : 0);
        }

        // logits = relu([out|context] @ Wl + bl)
        mma_gemm_kernel<1, 0><<<dim3(Vv / 128, 1), 256>>>(
            p_xl, 3 * Hh, Wl, 3 * Hh, nullptr, 0, nullptr, 0, Vv,
            bl, nullptr, p_logits, Vv, nullptr, nullptr, 0);

        softmax_v_kernel<<<Bsz, 1024>>>(out + (size_t)s * Bsz * Vv);
    }
    (void)in_sizes; (void)n_in; (void)out_size;
}

// round 3
// speedup vs baseline: 3.2873x; 1.0052x over previous
#include <cuda_runtime.h>
#include <math.h>
#include <stdint.h>

#define Bsz 64
#define TIN 128
#define TOUT 32
#define Vv 32000
#define Ee 512
#define Hh 1024
#define Aa 512
#define Ll 4

// ---------------- scratch (static device memory; no allocations) ----------------
__device__ __align__(16) float g_encproj[TIN * Bsz * Aa];
__device__ __align__(16) float g_dec[Bsz * Aa];
__device__ __align__(16) float g_scores[TIN * Bsz];
__device__ __align__(16) float g_x0[Bsz * (2 * Hh + Ee)];
__device__ __align__(16) float g_xl[Bsz * 3 * Hh];
__device__ __align__(16) float g_ha[Ll * Bsz * Hh];
__device__ __align__(16) float g_hb[Ll * Bsz * Hh];
__device__ __align__(16) float g_c[Ll * Bsz * Hh];
__device__ __align__(16) float g_out[Bsz * Hh];
__device__ __align__(16) float g_logits[(size_t)Bsz * Vv];
__device__ int g_tok[Bsz];

// ---------------- init ----------------
__global__ void init_state_kernel(const float* __restrict__ h0,
                                  const float* __restrict__ c0,
                                  const float* __restrict__ o0,
                                  const int* __restrict__ eos)
{
    int idx = blockIdx.x * blockDim.x + threadIdx.x;
    if (idx < Ll * Bsz * Hh) { g_ha[idx] = h0[idx]; g_c[idx] = c0[idx]; }
    if (idx < Bsz * Hh) g_out[idx] = o0[idx];
    if (idx < Bsz) g_tok[idx] = eos[0];
}

// ---------------- tf32 helpers ----------------
__device__ __forceinline__ uint32_t f2tf(float x)
{
    uint32_t u;
    asm("cvt.rna.tf32.f32 %0, %1;" : "=r"(u) : "f"(x));
    return u;
}

__device__ __forceinline__ void mma_tf32(float* c, const uint32_t* a, const uint32_t* b)
{
    asm volatile(
        "mma.sync.aligned.m16n8k8.row.col.f32.tf32.tf32.f32 "
        "{%0,%1,%2,%3}, {%4,%5,%6,%7}, {%8,%9}, {%0,%1,%2,%3};"
        : "+f"(c[0]), "+f"(c[1]), "+f"(c[2]), "+f"(c[3])
        : "r"(a[0]), "r"(a[1]), "r"(a[2]), "r"(a[3]), "r"(b[0]), "r"(b[1]));
}

__device__ __forceinline__ float sigmoidf_(float x) { return 1.f / (1.f + expf(-x)); }

// ---------------- tf32 MMA GEMM ----------------
// C[64 x 128-tile] = [A0 | A1] @ [B0 ; B1]  (segmented K), M block = 64 rows.
// 256 threads = 8 warps arranged 2(M) x 4(N). Warp: 32 rows x 32 cols.
// MODE 0: C = A@B (+bias). MODE 1: relu(A@B + bias). MODE 2: fused LSTM cell.
// GATED=1: B columns interleave the 4 LSTM gates at 8-col granularity so each
// warp's 4 n-tiles are gates i,f,g,o of the same hidden indices.
template <int MODE, int GATED>
__global__ __launch_bounds__(256) void mma_gemm_kernel(
    const float* __restrict__ A0, int lda0, const float* __restrict__ B0, int K0,
    const float* __restrict__ A1p, int lda1, const float* __restrict__ B1p, int K1,
    int ldb,
    const float* __restrict__ bias, const float* __restrict__ bias2,
    float* __restrict__ C, int ldc,
    float* __restrict__ cell, float* __restrict__ hout, int last)
{
    __shared__ uint32_t sA[64 * 36];   // [m][k] stride 36 (pad 4)
    __shared__ uint32_t sB[4096];      // 4 ksteps x (krow*128 + nin*16 + (nouter^swz))

    const int tid = threadIdx.x;
    const int lane = tid & 31;
    const int wid = tid >> 5;
    const int warpM = wid >> 2;     // 0..1
    const int warpN = wid & 3;      // 0..3
    const int M0 = blockIdx.y * 64;

    // global A load coords: 2 rows of float4 per thread
    const int am = tid >> 3;            // 0..31
    const int ak = (tid & 7) << 2;      // 0,4,...,28
    // global B load col (constant per thread)
    const int bn = lane << 2;           // 0..124
    int bcol;
    if (GATED)
        bcol = ((bn >> 3) & 3) * Hh + blockIdx.x * 32 + ((bn >> 5) << 3) + (bn & 7);
    else
        bcol = blockIdx.x * 128 + bn;

    const int nch0 = K0 >> 5;
    const int nch1 = K1 >> 5;
    const int ntot = nch0 + nch1;

    float4 rA0, rA1, rB[4];

    auto load_global = [&](int c) {
        const float* Ap;
        const float* Bp;
        int lda, k0;
        if (c < nch0) { Ap = A0; lda = lda0; Bp = B0; k0 = c << 5; }
        else { Ap = A1p; lda = lda1; Bp = B1p; k0 = (c - nch0) << 5; }
        rA0 = *(const float4*)(Ap + (size_t)(M0 + am) * lda + k0 + ak);
        rA1 = *(const float4*)(Ap + (size_t)(M0 + am + 32) * lda + k0 + ak);
#pragma unroll
        for (int r = 0; r < 4; r++)
            rB[r] = *(const float4*)(Bp + (size_t)(k0 + r * 8 + wid) * ldb + bcol);
    };

    float acc[2][4][4];
#pragma unroll
    for (int mt = 0; mt < 2; mt++)
#pragma unroll
        for (int t = 0; t < 4; t++)
#pragma unroll
            for (int j = 0; j < 4; j++) acc[mt][t][j] = 0.f;

    load_global(0);

    const int nin0 = (lane & 1) * 4;
    const int nout = lane >> 1;

    for (int c = 0; c < ntot; c++) {
        __syncthreads();
        // store A (tf32)
        {
            uint4 v0 = make_uint4(f2tf(rA0.x), f2tf(rA0.y), f2tf(rA0.z), f2tf(rA0.w));
            uint4 v1 = make_uint4(f2tf(rA1.x), f2tf(rA1.y), f2tf(rA1.z), f2tf(rA1.w));
            *(uint4*)&sA[am * 36 + ak] = v0;
            *(uint4*)&sA[(am + 32) * 36 + ak] = v1;
        }
        // store B (tf32, swizzled)
#pragma unroll
        for (int r = 0; r < 4; r++) {
            int base = r * 1024 + wid * 128;
            int sw = (wid & 3) * 4;
            sB[base + (nin0 + 0) * 16 + (nout ^ sw)] = f2tf(rB[r].x);
            sB[base + (nin0 + 1) * 16 + (nout ^ sw)] = f2tf(rB[r].y);
            sB[base + (nin0 + 2) * 16 + (nout ^ sw)] = f2tf(rB[r].z);
            sB[base + (nin0 + 3) * 16 + (nout ^ sw)] = f2tf(rB[r].w);
        }
        __syncthreads();
        if (c + 1 < ntot) load_global(c + 1);

#pragma unroll
        for (int ks = 0; ks < 4; ks++) {
            uint32_t a[2][4];
#pragma unroll
            for (int mt = 0; mt < 2; mt++) {
                int mrow = warpM * 32 + mt * 16 + (lane >> 2);
                const uint32_t* pa = &sA[mrow * 36 + ks * 8 + (lane & 3)];
                a[mt][0] = pa[0];
                a[mt][1] = pa[8 * 36];
                a[mt][2] = pa[4];
                a[mt][3] = pa[8 * 36 + 4];
            }
            int bbase = ks * 1024 + (lane & 3) * 128 + (lane >> 2) * 16 +
                        ((warpN * 4) ^ ((lane & 3) * 4));
            uint4 b0 = *(const uint4*)&sB[bbase];
            uint4 b1 = *(const uint4*)&sB[bbase + 512];
            uint32_t bb[4][2] = {{b0.x, b1.x}, {b0.y, b1.y}, {b0.z, b1.z}, {b0.w, b1.w}};
#pragma unroll
            for (int mt = 0; mt < 2; mt++)
#pragma unroll
                for (int t = 0; t < 4; t++)
                    mma_tf32(acc[mt][t], a[mt], bb[t]);
        }
    }

    // ------------- epilogue -------------
    if (MODE == 2) {
#pragma unroll
        for (int j = 0; j < 4; j++) {
            int idx = blockIdx.x * 32 + warpN * 8 + (lane & 3) * 2 + (j & 1);
            float bi = bias[idx] + bias2[idx];
            float bf = bias[Hh + idx] + bias2[Hh + idx];
            float bg = bias[2 * Hh + idx] + bias2[2 * Hh + idx];
            float bo = bias[3 * Hh + idx] + bias2[3 * Hh + idx];
#pragma unroll
            for (int mt = 0; mt < 2; mt++) {
                int row = warpM * 32 + mt * 16 + (lane >> 2) + ((j & 2) << 2);
                float iv = sigmoidf_(acc[mt][0][j] + bi);
                float fv = sigmoidf_(acc[mt][1][j] + bf);
                float gv = tanhf(acc[mt][2][j] + bg);
                float ov = sigmoidf_(acc[mt][3][j] + bo);
                size_t off = (size_t)row * Hh + idx;
                float cn = fv * cell[off] + iv * gv;
                float hn = ov * tanhf(cn);
                cell[off] = cn;
                hout[off] = hn;
                if (last) {
                    g_out[off] = hn;
                    g_xl[(size_t)row * 3 * Hh + idx] = hn;
                }
            }
        }
    } else {
#pragma unroll
        for (int mt = 0; mt < 2; mt++)
#pragma unroll
            for (int t = 0; t < 4; t++)
#pragma unroll
                for (int j = 0; j < 4; j++) {
                    int row = M0 + warpM * 32 + mt * 16 + (lane >> 2) + ((j & 2) << 2);
                    int col = blockIdx.x * 128 + warpN * 32 + t * 8 + (lane & 3) * 2 + (j & 1);
                    float v = acc[mt][t][j];
                    if (bias) v += bias[col];
                    if (MODE == 1) v = fmaxf(v, 0.f);
                    C[(size_t)row * ldc + col] = v;
                }
    }
}

// ---------------- attention scores ----------------
__global__ __launch_bounds__(256) void attn_scores_kernel(
    const float* __restrict__ is_on,
    const float* __restrict__ A2, const float* __restrict__ b2)
{
    const int t = blockIdx.x, b = blockIdx.y;
    const float* ep = g_encproj + ((size_t)t * Bsz + b) * Aa;
    const float* dp = g_dec + b * Aa;
    const int tid = threadIdx.x;
    float s = 0.f;
#pragma unroll
    for (int a = tid; a < Aa; a += 256)
        s += tanhf(ep[a] + dp[a]) * A2[a];
    __shared__ float red[256];
    red[tid] = s;
    __syncthreads();
    for (int st = 128; st > 0; st >>= 1) {
        if (tid < st) red[tid] += red[tid + st];
        __syncthreads();
    }
    if (tid == 0)
        g_scores[t * Bsz + b] = red[0] + b2[0] + (1.f - is_on[t * Bsz + b]) * (-1e30f);
}

// ---------------- softmax over T + context ----------------
__global__ __launch_bounds__(256) void attn_context_kernel(const float* __restrict__ enc)
{
    const int b = blockIdx.x;
    const int dchunk = blockIdx.y;
    const int tid = threadIdx.x;
    __shared__ float sAlpha[TIN];
    __shared__ float red[256];

    float v = (tid < TIN) ? g_scores[tid * Bsz + b] : -3.4e38f;
    red[tid] = v;
    __syncthreads();
    for (int st = 128; st > 0; st >>= 1) {
        if (tid < st) red[tid] = fmaxf(red[tid], red[tid + st]);
        __syncthreads();
    }
    float mx = red[0];
    __syncthreads();
    float e = (tid < TIN) ? expf(v - mx) : 0.f;
    if (tid < TIN) sAlpha[tid] = e;
    red[tid] = e;
    __syncthreads();
    for (int st = 128; st > 0; st >>= 1) {
        if (tid < st) red[tid] += red[tid + st];
        __syncthreads();
    }
    float inv = 1.f / red[0];

    const int d = dchunk * 256 + tid;
    const float* ep = enc + (size_t)b * (2 * Hh) + d;
    float acc = 0.f;
#pragma unroll 4
    for (int t = 0; t < TIN; t++)
        acc += sAlpha[t] * ep[(size_t)t * Bsz * 2 * Hh];
    float ctx = acc * inv;
    g_x0[b * (2 * Hh + Ee) + d] = ctx;
    g_xl[b * 3 * Hh + Hh + d] = ctx;
}

// ---------------- embedding gather ----------------
__global__ void gather_emb_kernel(const float* __restrict__ emb)
{
    const int b = blockIdx.x;
    const int e = blockIdx.y * 256 + threadIdx.x;
    g_x0[b * (2 * Hh + Ee) + 2 * Hh + e] = emb[(size_t)g_tok[b] * Ee + e];
}

// ---------------- softmax over V + argmax ----------------
__global__ __launch_bounds__(1024) void softmax_v_kernel(float* __restrict__ probs)
{
    const int b = blockIdx.x;
    const float* lr = g_logits + (size_t)b * Vv;
    const int tid = threadIdx.x;
    __shared__ float rv[1024];
    __shared__ int ri[1024];

    float m = -3.4e38f;
    int mi = 0;
    for (int i = tid; i < Vv; i += 1024) {
        float x = lr[i];
        if (x > m) { m = x; mi = i; }
    }
    rv[tid] = m; ri[tid] = mi;
    __syncthreads();
    for (int st = 512; st > 0; st >>= 1) {
        if (tid < st) {
            float vo = rv[tid + st]; int io = ri[tid + st];
            if (vo > rv[tid] || (vo == rv[tid] && io < ri[tid])) { rv[tid] = vo; ri[tid] = io; }
        }
        __syncthreads();
    }
    float mx = rv[0];
    if (tid == 0) g_tok[b] = ri[0];
    __syncthreads();

    float s = 0.f;
    for (int i = tid; i < Vv; i += 1024) s += expf(lr[i] - mx);
    rv[tid] = s;
    __syncthreads();
    for (int st = 512; st > 0; st >>= 1) {
        if (tid < st) rv[tid] += rv[tid + st];
        __syncthreads();
    }
    float inv = 1.f / rv[0];
    float* pr = probs + (size_t)b * Vv;
    for (int i = tid; i < Vv; i += 1024) pr[i] = expf(lr[i] - mx) * inv;
}

// ---------------- host orchestration ----------------
extern "C" void kernel_launch(void* const* d_in, const int* in_sizes, int n_in,
                              void* d_out, int out_size)
{
    const float* enc   = (const float*)d_in[0];
    const float* is_on = (const float*)d_in[1];
    const float* emb   = (const float*)d_in[2];
    const float* A1    = (const float*)d_in[3];
    const float* b1    = (const float*)d_in[4];
    const float* A2    = (const float*)d_in[5];
    const float* b2    = (const float*)d_in[6];
    const float* W_ih0 = (const float*)d_in[7];
    const float* W_ihr = (const float*)d_in[8];
    const float* W_hh  = (const float*)d_in[9];
    const float* b_ih  = (const float*)d_in[10];
    const float* b_hh  = (const float*)d_in[11];
    const float* Wl    = (const float*)d_in[12];
    const float* bl    = (const float*)d_in[13];
    const float* h0    = (const float*)d_in[14];
    const float* c0    = (const float*)d_in[15];
    const float* o0    = (const float*)d_in[16];
    const int*   eos   = (const int*)d_in[17];
    float* out = (float*)d_out;

    float *p_encproj, *p_dec, *p_x0, *p_xl, *p_ha, *p_hb, *p_c, *p_out, *p_logits;
    cudaGetSymbolAddress((void**)&p_encproj, g_encproj);
    cudaGetSymbolAddress((void**)&p_dec, g_dec);
    cudaGetSymbolAddress((void**)&p_x0, g_x0);
    cudaGetSymbolAddress((void**)&p_xl, g_xl);
    cudaGetSymbolAddress((void**)&p_ha, g_ha);
    cudaGetSymbolAddress((void**)&p_hb, g_hb);
    cudaGetSymbolAddress((void**)&p_c, g_c);
    cudaGetSymbolAddress((void**)&p_out, g_out);
    cudaGetSymbolAddress((void**)&p_logits, g_logits);

    init_state_kernel<<<(Ll * Bsz * Hh + 255) / 256, 256>>>(h0, c0, o0, eos);

    // enc_proj = enc @ A1[H:]   (8192 x 512, K=2048)
    mma_gemm_kernel<0, 0><<<dim3(4, 128), 256>>>(
        enc, 2 * Hh, A1 + (size_t)Hh * Aa, 2 * Hh,
        nullptr, 0, nullptr, 0, Aa,
        nullptr, nullptr, p_encproj, Aa, nullptr, nullptr, 0);

    for (int s = 0; s < TOUT; s++) {
        float* hold = (s & 1) ? p_hb : p_ha;
        float* hnew = (s & 1) ? p_ha : p_hb;

        // dec = out_prev @ A1[:H] + b1
        mma_gemm_kernel<0, 0><<<dim3(4, 1), 256>>>(
            p_out, Hh, A1, Hh, nullptr, 0, nullptr, 0, Aa,
            b1, nullptr, p_dec, Aa, nullptr, nullptr, 0);

        attn_scores_kernel<<<dim3(TIN, Bsz), 256>>>(is_on, A2, b2);
        attn_context_kernel<<<dim3(Bsz, (2 * Hh) / 256), 256>>>(enc);
        gather_emb_kernel<<<dim3(Bsz, Ee / 256), 256>>>(emb);

        for (int l = 0; l < Ll; l++) {
            const float* x = (l == 0) ? p_x0 : (hnew + (size_t)(l - 1) * Bsz * Hh);
            int Kx = (l == 0) ? (2 * Hh + Ee) : Hh;
            const float* Wih = (l == 0) ? W_ih0 : (W_ihr + (size_t)(l - 1) * Hh * 4 * Hh);
            mma_gemm_kernel<2, 1><<<dim3(32, 1), 256>>>(
                x, Kx, Wih, Kx,
                hold + (size_t)l * Bsz * Hh, Hh, W_hh + (size_t)l * Hh * 4 * Hh, Hh,
                4 * Hh,
                b_ih + (size_t)l * 4 * Hh, b_hh + (size_t)l * 4 * Hh,
                nullptr, 0,
                p_c + (size_t)l * Bsz * Hh, hnew + (size_t)l * Bsz * Hh,
                (l == Ll - 1) ? 1 : 0);
        }

        // logits = relu([out|context] @ Wl + bl)
        mma_gemm_kernel<1, 0><<<dim3(Vv / 128, 1), 256>>>(
            p_xl, 3 * Hh, Wl, 3 * Hh, nullptr, 0, nullptr, 0, Vv,
            bl, nullptr, p_logits, Vv, nullptr, nullptr, 0);

        softmax_v_kernel<<<Bsz, 1024>>>(out + (size_t)s * Bsz * Vv);
    }
    (void)in_sizes; (void)n_in; (void)out_size;
}

// round 4
// speedup vs baseline: 3.3653x; 1.0237x over previous
#include <cuda_runtime.h>
#include <math.h>
#include <stdint.h>

#define Bsz 64
#define TIN 128
#define TOUT 32
#define Vv 32000
#define Ee 512
#define Hh 1024
#define Aa 512
#define Ll 4
#define NSEG 8
#define SEGV (Vv / NSEG)

// GEMM tiling
#define BM 64
#define BN 256
#define BK 32
#define AST 36
#define BST 264
#define ASZ (BM * AST)          // 2304 floats
#define BSZW (BK * BST)         // 8448 floats
#define STAGE_F (ASZ + BSZW)    // 10752 floats
#define SMEMB (STAGE_F * 4 * 3) // 129024 bytes

// ---------------- scratch ----------------
__device__ __align__(16) float g_encproj[TIN * Bsz * Aa];
__device__ __align__(16) float g_dec[Bsz * Aa];
__device__ __align__(16) float g_scores[TIN * Bsz];
__device__ __align__(16) float g_x0[Bsz * (2 * Hh + Ee)];
__device__ __align__(16) float g_xl[Bsz * 3 * Hh];
__device__ __align__(16) float g_ha[Ll * Bsz * Hh];
__device__ __align__(16) float g_hb[Ll * Bsz * Hh];
__device__ __align__(16) float g_c[Ll * Bsz * Hh];
__device__ __align__(16) float g_out[Bsz * Hh];
__device__ __align__(16) float g_rec[Ll * Bsz * 4 * Hh];
__device__ __align__(16) float g_logits[(size_t)Bsz * Vv];
__device__ int g_tok[Bsz];
__device__ float g_pmax[Bsz * NSEG], g_psum[Bsz * NSEG];
__device__ int g_pidx[Bsz * NSEG];

// ---------------- init ----------------
__global__ void init_state_kernel(const float* __restrict__ h0,
                                  const float* __restrict__ c0,
                                  const float* __restrict__ o0,
                                  const int* __restrict__ eos)
{
    int idx = blockIdx.x * blockDim.x + threadIdx.x;
    if (idx < Ll * Bsz * Hh) { g_ha[idx] = h0[idx]; g_c[idx] = c0[idx]; }
    if (idx < Bsz * Hh) g_out[idx] = o0[idx];
    if (idx < Bsz) g_tok[idx] = eos[0];
}

// ---------------- helpers ----------------
__device__ __forceinline__ void cp16(uint32_t dst, const void* src)
{
    asm volatile("cp.async.cg.shared.global [%0], [%1], 16;\n" :: "r"(dst), "l"(src));
}
__device__ __forceinline__ void cpcommit() { asm volatile("cp.async.commit_group;\n"); }
template <int N>
__device__ __forceinline__ void cpwait() { asm volatile("cp.async.wait_group %0;\n" :: "n"(N)); }

__device__ __forceinline__ void mma_tf32(float* c, const uint32_t* a, const uint32_t* b)
{
    asm volatile(
        "mma.sync.aligned.m16n8k8.row.col.f32.tf32.tf32.f32 "
        "{%0,%1,%2,%3}, {%4,%5,%6,%7}, {%8,%9}, {%0,%1,%2,%3};"
        : "+f"(c[0]), "+f"(c[1]), "+f"(c[2]), "+f"(c[3])
        : "r"(a[0]), "r"(a[1]), "r"(a[2]), "r"(a[3]), "r"(b[0]), "r"(b[1]));
}

__device__ __forceinline__ float sigmoidf_(float x) { return 1.f / (1.f + expf(-x)); }

// ---------------- pipelined tf32 GEMM ----------------
// Tile 64x256, 128 threads (4 warps, each 64Mx64N), 3-stage cp.async, K-chunk 32.
// MODE 0: C = A@B (+bias). MODE 1: relu(A@B+bias). MODE 2: fused LSTM cell.
// GATED: B columns gate-interleaved (block covers 64 hidden idx x 4 gates).
template <int MODE, int GATED>
__global__ void __launch_bounds__(128) gemm3_kernel(
    const float* __restrict__ A, int lda, long zsA,
    const float* __restrict__ Bm, long zsB, int ldb,
    const float* __restrict__ bias,
    float* __restrict__ C, int ldc, long zsC,
    int K,
    const float* __restrict__ rec,
    const float* __restrict__ bih, const float* __restrict__ bhh,
    float* __restrict__ cell, float* __restrict__ hout, int last)
{
    extern __shared__ float sm[];
    A += blockIdx.z * zsA;
    Bm += blockIdx.z * zsB;
    if (C) C += blockIdx.z * zsC;
    if (MODE == 2) { /* rec/cell/hout offsets applied by host */ }
    const int tid = threadIdx.x;
    const int lane = tid & 31;
    const int w = tid >> 5;
    const int M0 = blockIdx.y * BM;
    const int bx = blockIdx.x;

    const uint32_t smb = (uint32_t)__cvta_generic_to_shared(sm);
    const int nch = K / BK;

    auto issue = [&](int c, int s) {
        uint32_t sa = smb + (uint32_t)s * (STAGE_F * 4);
        uint32_t sb = sa + ASZ * 4;
        int k0 = c * BK;
#pragma unroll
        for (int i = 0; i < 4; i++) {
            int cid = tid + i * 128;
            int row = cid >> 3, kq = (cid & 7) << 2;
            cp16(sa + (uint32_t)(row * AST + kq) * 4,
                 A + (size_t)(M0 + row) * lda + k0 + kq);
        }
#pragma unroll
        for (int i = 0; i < 16; i++) {
            int cid = tid + i * 128;
            int kr = cid >> 6, nq = (cid & 63) << 2;
            int gcol;
            if (GATED) {
                int q = nq & 63, wn = nq >> 6;
                gcol = ((q >> 3) & 3) * Hh + bx * 64 + wn * 16 + ((q >> 5) << 3) + (q & 7);
            } else {
                gcol = bx * BN + nq;
            }
            cp16(sb + (uint32_t)(kr * BST + nq) * 4,
                 Bm + (size_t)(k0 + kr) * ldb + gcol);
        }
        cpcommit();
    };

    float acc[4][8][4];
#pragma unroll
    for (int mt = 0; mt < 4; mt++)
#pragma unroll
        for (int t = 0; t < 8; t++)
#pragma unroll
            for (int j = 0; j < 4; j++) acc[mt][t][j] = 0.f;

    issue(0, 0);
    if (nch > 1) issue(1, 1);

    for (int c = 0; c < nch; c++) {
        cpwait<1>();
        __syncthreads();
        if (c + 2 < nch) issue(c + 2, (c + 2) % 3);

        const uint32_t* uA = (const uint32_t*)(sm + (c % 3) * STAGE_F);
        const uint32_t* uB = uA + ASZ;
#pragma unroll
        for (int ks = 0; ks < 4; ks++) {
            uint32_t af[4][4];
            const int ac = ks * 8 + (lane & 3);
            const int ar = lane >> 2;
#pragma unroll
            for (int mt = 0; mt < 4; mt++) {
                const uint32_t* p = uA + (mt * 16 + ar) * AST + ac;
                af[mt][0] = p[0];
                af[mt][1] = p[8 * AST];
                af[mt][2] = p[4];
                af[mt][3] = p[8 * AST + 4];
            }
            uint32_t bf[8][2];
            const int bk = ks * 8 + (lane & 3);
            const int bn = w * 64 + (lane >> 2);
#pragma unroll
            for (int t = 0; t < 8; t++) {
                bf[t][0] = uB[bk * BST + bn + t * 8];
                bf[t][1] = uB[(bk + 4) * BST + bn + t * 8];
            }
#pragma unroll
            for (int mt = 0; mt < 4; mt++)
#pragma unroll
                for (int t = 0; t < 8; t++)
                    mma_tf32(acc[mt][t], af[mt], bf[t]);
        }
        __syncthreads();
    }

    // ---------------- epilogue ----------------
    if (MODE == 2) {
        const int r0 = lane >> 2;
        const int cb = (lane & 3) * 2;
#pragma unroll
        for (int mt = 0; mt < 4; mt++)
#pragma unroll
            for (int tt = 0; tt < 2; tt++)
#pragma unroll
                for (int j = 0; j < 4; j++) {
                    int row = mt * 16 + r0 + (j >> 1) * 8;
                    int hid = bx * 64 + w * 16 + tt * 8 + cb + (j & 1);
                    int recb = row * (4 * Hh) + bx * 256 + w * 64 + tt * 32 + cb + (j & 1);
                    float xi = acc[mt][tt * 4 + 0][j] + rec[recb + 0]  + bih[hid]          + bhh[hid];
                    float xf = acc[mt][tt * 4 + 1][j] + rec[recb + 8]  + bih[Hh + hid]     + bhh[Hh + hid];
                    float xg = acc[mt][tt * 4 + 2][j] + rec[recb + 16] + bih[2 * Hh + hid] + bhh[2 * Hh + hid];
                    float xo = acc[mt][tt * 4 + 3][j] + rec[recb + 24] + bih[3 * Hh + hid] + bhh[3 * Hh + hid];
                    float iv = sigmoidf_(xi);
                    float fv = sigmoidf_(xf);
                    float gv = tanhf(xg);
                    float ov = sigmoidf_(xo);
                    size_t off = (size_t)row * Hh + hid;
                    float cn = fv * cell[off] + iv * gv;
                    float hn = ov * tanhf(cn);
                    cell[off] = cn;
                    hout[off] = hn;
                    if (last) {
                        g_out[off] = hn;
                        g_xl[(size_t)row * 3 * Hh + hid] = hn;
                    }
                }
    } else {
        const int r0 = lane >> 2;
        const int cb = (lane & 3) * 2;
#pragma unroll
        for (int mt = 0; mt < 4; mt++) {
            int ra = M0 + mt * 16 + r0;
#pragma unroll
            for (int t = 0; t < 8; t++) {
                int col = bx * BN + w * 64 + t * 8 + cb;
                float b0 = bias ? bias[col] : 0.f;
                float b1 = bias ? bias[col + 1] : 0.f;
                float v0 = acc[mt][t][0] + b0, v1 = acc[mt][t][1] + b1;
                float v2 = acc[mt][t][2] + b0, v3 = acc[mt][t][3] + b1;
                if (MODE == 1) {
                    v0 = fmaxf(v0, 0.f); v1 = fmaxf(v1, 0.f);
                    v2 = fmaxf(v2, 0.f); v3 = fmaxf(v3, 0.f);
                }
                *(float2*)&C[(size_t)ra * ldc + col] = make_float2(v0, v1);
                *(float2*)&C[(size_t)(ra + 8) * ldc + col] = make_float2(v2, v3);
            }
        }
    }
}

// ---------------- attention scores ----------------
__global__ __launch_bounds__(128) void attn_scores_kernel(
    const float* __restrict__ is_on,
    const float* __restrict__ A2, const float* __restrict__ b2)
{
    const int t = blockIdx.x, b = blockIdx.y;
    const int tid = threadIdx.x;
    const float4 e = ((const float4*)(g_encproj + ((size_t)t * Bsz + b) * Aa))[tid];
    const float4 d = ((const float4*)(g_dec + b * Aa))[tid];
    const float4 a = ((const float4*)A2)[tid];
    float s = tanhf(e.x + d.x) * a.x + tanhf(e.y + d.y) * a.y +
              tanhf(e.z + d.z) * a.z + tanhf(e.w + d.w) * a.w;
#pragma unroll
    for (int o = 16; o > 0; o >>= 1) s += __shfl_down_sync(0xffffffffu, s, o);
    __shared__ float ws[4];
    if ((tid & 31) == 0) ws[tid >> 5] = s;
    __syncthreads();
    if (tid == 0) {
        float tot = ws[0] + ws[1] + ws[2] + ws[3];
        g_scores[t * Bsz + b] = tot + b2[0] + (1.f - is_on[t * Bsz + b]) * (-1e30f);
    }
}

// ---------------- softmax over T + context ----------------
__global__ __launch_bounds__(256) void attn_context_kernel(const float* __restrict__ enc)
{
    const int b = blockIdx.x;
    const int dchunk = blockIdx.y;
    const int tid = threadIdx.x;
    __shared__ float sAlpha[TIN];
    __shared__ float red[256];

    float v = (tid < TIN) ? g_scores[tid * Bsz + b] : -3.4e38f;
    red[tid] = v;
    __syncthreads();
    for (int st = 128; st > 0; st >>= 1) {
        if (tid < st) red[tid] = fmaxf(red[tid], red[tid + st]);
        __syncthreads();
    }
    float mx = red[0];
    __syncthreads();
    float e = (tid < TIN) ? expf(v - mx) : 0.f;
    if (tid < TIN) sAlpha[tid] = e;
    red[tid] = e;
    __syncthreads();
    for (int st = 128; st > 0; st >>= 1) {
        if (tid < st) red[tid] += red[tid + st];
        __syncthreads();
    }
    float inv = 1.f / red[0];

    const int d = dchunk * 256 + tid;
    const float* ep = enc + (size_t)b * (2 * Hh) + d;
    float acc = 0.f;
#pragma unroll 4
    for (int t = 0; t < TIN; t++)
        acc += sAlpha[t] * ep[(size_t)t * Bsz * 2 * Hh];
    float ctx = acc * inv;
    g_x0[b * (2 * Hh + Ee) + d] = ctx;
    g_xl[b * 3 * Hh + Hh + d] = ctx;
}

// ---------------- embedding gather ----------------
__global__ void gather_emb_kernel(const float* __restrict__ emb)
{
    const int b = blockIdx.x;
    const int e = blockIdx.y * 256 + threadIdx.x;
    g_x0[b * (2 * Hh + Ee) + 2 * Hh + e] = emb[(size_t)g_tok[b] * Ee + e];
}

// ---------------- softmax over V, 4-phase ----------------
__global__ __launch_bounds__(256) void smax_seg_kernel()
{
    const int b = blockIdx.x, s = blockIdx.y;
    const float* lr = g_logits + (size_t)b * Vv + s * SEGV;
    const int tid = threadIdx.x;
    __shared__ float rv[256];
    __shared__ int ri[256];
    float m = -3.4e38f;
    int mi = 0;
    for (int i = tid; i < SEGV; i += 256) {
        float x = lr[i];
        if (x > m) { m = x; mi = s * SEGV + i; }
    }
    rv[tid] = m; ri[tid] = mi;
    __syncthreads();
    for (int st = 128; st > 0; st >>= 1) {
        if (tid < st) {
            float vo = rv[tid + st]; int io = ri[tid + st];
            if (vo > rv[tid] || (vo == rv[tid] && io < ri[tid])) { rv[tid] = vo; ri[tid] = io; }
        }
        __syncthreads();
    }
    if (tid == 0) { g_pmax[b * NSEG + s] = rv[0]; g_pidx[b * NSEG + s] = ri[0]; }
}

__global__ void smax_tok_kernel()
{
    const int b = blockIdx.x;
    if (threadIdx.x == 0) {
        float m = g_pmax[b * NSEG];
        int mi = g_pidx[b * NSEG];
        for (int s = 1; s < NSEG; s++) {
            float v = g_pmax[b * NSEG + s];
            int i = g_pidx[b * NSEG + s];
            if (v > m || (v == m && i < mi)) { m = v; mi = i; }
        }
        g_tok[b] = mi;
    }
}

__global__ __launch_bounds__(256) void smax_exp_kernel(float* __restrict__ outp)
{
    const int b = blockIdx.x, s = blockIdx.y;
    const int tid = threadIdx.x;
    float gm = g_pmax[b * NSEG];
#pragma unroll
    for (int k = 1; k < NSEG; k++) gm = fmaxf(gm, g_pmax[b * NSEG + k]);
    const float4* lr4 = (const float4*)(g_logits + (size_t)b * Vv + s * SEGV);
    float4* o4 = (float4*)(outp + (size_t)b * Vv + s * SEGV);
    float sum = 0.f;
    for (int i = tid; i < SEGV / 4; i += 256) {
        float4 x = lr4[i];
        float4 e = make_float4(expf(x.x - gm), expf(x.y - gm), expf(x.z - gm), expf(x.w - gm));
        o4[i] = e;
        sum += e.x + e.y + e.z + e.w;
    }
    __shared__ float rv[256];
    rv[tid] = sum;
    __syncthreads();
    for (int st = 128; st > 0; st >>= 1) {
        if (tid < st) rv[tid] += rv[tid + st];
        __syncthreads();
    }
    if (tid == 0) g_psum[b * NSEG + s] = rv[0];
}

__global__ __launch_bounds__(256) void smax_scale_kernel(float* __restrict__ outp)
{
    const int b = blockIdx.x, s = blockIdx.y;
    const int tid = threadIdx.x;
    float tot = 0.f;
#pragma unroll
    for (int k = 0; k < NSEG; k++) tot += g_psum[b * NSEG + k];
    const float inv = 1.f / tot;
    float4* o4 = (float4*)(outp + (size_t)b * Vv + s * SEGV);
    for (int i = tid; i < SEGV / 4; i += 256) {
        float4 e = o4[i];
        o4[i] = make_float4(e.x * inv, e.y * inv, e.z * inv, e.w * inv);
    }
}

// ---------------- host orchestration ----------------
extern "C" void kernel_launch(void* const* d_in, const int* in_sizes, int n_in,
                              void* d_out, int out_size)
{
    const float* enc   = (const float*)d_in[0];
    const float* is_on = (const float*)d_in[1];
    const float* emb   = (const float*)d_in[2];
    const float* A1    = (const float*)d_in[3];
    const float* b1    = (const float*)d_in[4];
    const float* A2    = (const float*)d_in[5];
    const float* b2    = (const float*)d_in[6];
    const float* W_ih0 = (const float*)d_in[7];
    const float* W_ihr = (const float*)d_in[8];
    const float* W_hh  = (const float*)d_in[9];
    const float* b_ih  = (const float*)d_in[10];
    const float* b_hh  = (const float*)d_in[11];
    const float* Wl    = (const float*)d_in[12];
    const float* bl    = (const float*)d_in[13];
    const float* h0    = (const float*)d_in[14];
    const float* c0    = (const float*)d_in[15];
    const float* o0    = (const float*)d_in[16];
    const int*   eos   = (const int*)d_in[17];
    float* out = (float*)d_out;

    float *p_encproj, *p_dec, *p_x0, *p_xl, *p_ha, *p_hb, *p_c, *p_out, *p_rec, *p_logits;
    cudaGetSymbolAddress((void**)&p_encproj, g_encproj);
    cudaGetSymbolAddress((void**)&p_dec, g_dec);
    cudaGetSymbolAddress((void**)&p_x0, g_x0);
    cudaGetSymbolAddress((void**)&p_xl, g_xl);
    cudaGetSymbolAddress((void**)&p_ha, g_ha);
    cudaGetSymbolAddress((void**)&p_hb, g_hb);
    cudaGetSymbolAddress((void**)&p_c, g_c);
    cudaGetSymbolAddress((void**)&p_out, g_out);
    cudaGetSymbolAddress((void**)&p_rec, g_rec);
    cudaGetSymbolAddress((void**)&p_logits, g_logits);

    cudaFuncSetAttribute(gemm3_kernel<0, 0>, cudaFuncAttributeMaxDynamicSharedMemorySize, SMEMB);
    cudaFuncSetAttribute(gemm3_kernel<1, 0>, cudaFuncAttributeMaxDynamicSharedMemorySize, SMEMB);
    cudaFuncSetAttribute(gemm3_kernel<0, 1>, cudaFuncAttributeMaxDynamicSharedMemorySize, SMEMB);
    cudaFuncSetAttribute(gemm3_kernel<2, 1>, cudaFuncAttributeMaxDynamicSharedMemorySize, SMEMB);

    init_state_kernel<<<(Ll * Bsz * Hh + 255) / 256, 256>>>(h0, c0, o0, eos);

    // enc_proj = enc @ A1[H:]   (8192 x 512, K=2048)
    gemm3_kernel<0, 0><<<dim3(2, 128), 128, SMEMB>>>(
        enc, 2 * Hh, 0, A1 + (size_t)Hh * Aa, 0, Aa,
        nullptr, p_encproj, Aa, 0, 2 * Hh,
        nullptr, nullptr, nullptr, nullptr, nullptr, 0);

    for (int s = 0; s < TOUT; s++) {
        float* hold = (s & 1) ? p_hb : p_ha;
        float* hnew = (s & 1) ? p_ha : p_hb;

        // dec = out_prev @ A1[:H] + b1   (64 x 512, K=1024)
        gemm3_kernel<0, 0><<<dim3(2, 1), 128, SMEMB>>>(
            p_out, Hh, 0, A1, 0, Aa,
            b1, p_dec, Aa, 0, Hh,
            nullptr, nullptr, nullptr, nullptr, nullptr, 0);

        attn_scores_kernel<<<dim3(TIN, Bsz), 128>>>(is_on, A2, b2);
        attn_context_kernel<<<dim3(Bsz, (2 * Hh) / 256), 256>>>(enc);
        gather_emb_kernel<<<dim3(Bsz, Ee / 256), 256>>>(emb);

        // recurrent partials for ALL layers: rec[l] = h_old[l] @ W_hh[l] (gate-interleaved)
        gemm3_kernel<0, 1><<<dim3(16, 1, Ll), 128, SMEMB>>>(
            hold, Hh, (long)Bsz * Hh, W_hh, (long)Hh * 4 * Hh, 4 * Hh,
            nullptr, p_rec, 4 * Hh, (long)Bsz * 4 * Hh, Hh,
            nullptr, nullptr, nullptr, nullptr, nullptr, 0);

        for (int l = 0; l < Ll; l++) {
            const float* x = (l == 0) ? p_x0 : (hnew + (size_t)(l - 1) * Bsz * Hh);
            int Kx = (l == 0) ? (2 * Hh + Ee) : Hh;
            const float* Wih = (l == 0) ? W_ih0 : (W_ihr + (size_t)(l - 1) * Hh * 4 * Hh);
            gemm3_kernel<2, 1><<<dim3(16, 1), 128, SMEMB>>>(
                x, Kx, 0, Wih, 0, 4 * Hh,
                nullptr, nullptr, 0, 0, Kx,
                p_rec + (size_t)l * Bsz * 4 * Hh,
                b_ih + (size_t)l * 4 * Hh, b_hh + (size_t)l * 4 * Hh,
                p_c + (size_t)l * Bsz * Hh, hnew + (size_t)l * Bsz * Hh,
                (l == Ll - 1) ? 1 : 0);
        }

        // logits = relu([out|context] @ Wl + bl)   (64 x 32000, K=3072)
        gemm3_kernel<1, 0><<<dim3(Vv / BN, 1), 128, SMEMB>>>(
            p_xl, 3 * Hh, 0, Wl, 0, Vv,
            bl, p_logits, Vv, 0, 3 * Hh,
            nullptr, nullptr, nullptr, nullptr, nullptr, 0);

        smax_seg_kernel<<<dim3(Bsz, NSEG), 256>>>();
        smax_tok_kernel<<<Bsz, 32>>>();
        smax_exp_kernel<<<dim3(Bsz, NSEG), 256>>>(out + (size_t)s * Bsz * Vv);
        smax_scale_kernel<<<dim3(Bsz, NSEG), 256>>>(out + (size_t)s * Bsz * Vv);
    }
    (void)in_sizes; (void)n_in; (void)out_size;
}

// round 5
// speedup vs baseline: 5.5150x; 1.6388x over previous
#include <cuda_runtime.h>
#include <cuda_fp16.h>
#include <math.h>
#include <stdint.h>

#define Bsz 64
#define TIN 128
#define TOUT 32
#define Vv 32000
#define Ee 512
#define Hh 1024
#define Aa 512
#define Ll 4
#define NSEG 8
#define SEGV (Vv / NSEG)

// GEMM tiling (fp16, k-paired u32 domain)
#define BM 64
#define BN 256
#define BK 32                   // halves per K-chunk
#define KU (BK / 2)             // 16 u32 per A row per chunk
#define ASTU 20                 // A smem row stride (u32, pad 4)
#define BSTU 264                // B smem row stride (u32, pad 8)
#define ASZU (BM * ASTU)        // 1280
#define BSZU (KU * BSTU)        // 4224
#define STAGEU (ASZU + BSZU)    // 5504 u32
#define SMEMB (STAGEU * 4 * 3)  // 66048 B, 3 stages

// ---------------- fp16 packed weights (filled per launch) ----------------
__device__ __align__(16) uint32_t g_Wl16[(size_t)(3 * Hh / 2) * Vv];     // 49.15M u32
__device__ __align__(16) uint32_t g_Wih016[(2 * Hh + Ee) / 2 * 4 * Hh];
__device__ __align__(16) uint32_t g_Wihr16[3][(Hh / 2) * 4 * Hh];
__device__ __align__(16) uint32_t g_Whh16[Ll][(Hh / 2) * 4 * Hh];
__device__ __align__(16) uint32_t g_A1lo16[(Hh / 2) * Aa];
__device__ __align__(16) uint32_t g_A1hi16[Hh * Aa];                     // K=2048 -> 1024 rows
__device__ __align__(16) __half g_emb16[(size_t)Vv * Ee];
__device__ __align__(16) __half g_enc16[(size_t)TIN * Bsz * 2 * Hh];

// ---------------- scratch ----------------
__device__ __align__(16) __half g_encproj16[(size_t)TIN * Bsz * Aa];
__device__ __align__(16) float g_dec[Bsz * Aa];
__device__ __align__(16) float g_scores[TIN * Bsz];
__device__ __align__(16) __half g_x016[Bsz * (2 * Hh + Ee)];
__device__ __align__(16) __half g_xl16[Bsz * 3 * Hh];
__device__ __align__(16) __half g_h16a[Ll * Bsz * Hh];
__device__ __align__(16) __half g_h16b[Ll * Bsz * Hh];
__device__ __align__(16) float g_c[Ll * Bsz * Hh];
__device__ __align__(16) __half g_out16[Bsz * Hh];
__device__ __align__(16) float g_rec[Ll * Bsz * 4 * Hh];
__device__ __align__(16) float g_logits[(size_t)Bsz * Vv];
__device__ int g_tok[Bsz];
__device__ float g_pmax[Bsz * NSEG], g_psum[Bsz * NSEG];
__device__ int g_pidx[Bsz * NSEG];

// ---------------- helpers ----------------
__device__ __forceinline__ uint32_t pack2(float lo, float hi)
{
    __half2 h = __floats2half2_rn(lo, hi);
    return *(uint32_t*)&h;
}

__device__ __forceinline__ void cp16(uint32_t dst, const void* src)
{
    asm volatile("cp.async.cg.shared.global [%0], [%1], 16;\n" :: "r"(dst), "l"(src));
}
__device__ __forceinline__ void cpcommit() { asm volatile("cp.async.commit_group;\n"); }
template <int N>
__device__ __forceinline__ void cpwait() { asm volatile("cp.async.wait_group %0;\n" :: "n"(N)); }

__device__ __forceinline__ void mma_f16(float* c, const uint32_t* a, const uint32_t* b)
{
    asm volatile(
        "mma.sync.aligned.m16n8k16.row.col.f32.f16.f16.f32 "
        "{%0,%1,%2,%3}, {%4,%5,%6,%7}, {%8,%9}, {%0,%1,%2,%3};"
        : "+f"(c[0]), "+f"(c[1]), "+f"(c[2]), "+f"(c[3])
        : "r"(a[0]), "r"(a[1]), "r"(a[2]), "r"(a[3]), "r"(b[0]), "r"(b[1]));
}

__device__ __forceinline__ float sigmoidf_(float x) { return 1.f / (1.f + expf(-x)); }

// ---------------- weight packing / conversion ----------------
// plain: out[k2*N + n] = half2(in[2k2][n], in[2k2+1][n])
__global__ void pack_plain_kernel(const float* __restrict__ in, uint32_t* __restrict__ out, int N)
{
    const int k2 = blockIdx.y;
    const int n = blockIdx.x * 256 + threadIdx.x;
    if (n < N)
        out[(size_t)k2 * N + n] =
            pack2(in[(size_t)(2 * k2) * N + n], in[(size_t)(2 * k2 + 1) * N + n]);
}

// gated: bake the LSTM gate interleave into the packed column order
__global__ void pack_gated_kernel(const float* __restrict__ in, uint32_t* __restrict__ out,
                                  long inStride, long outStride)
{
    in += blockIdx.z * inStride;
    out += blockIdx.z * outStride;
    const int k2 = blockIdx.y;
    const int p = blockIdx.x * 256 + threadIdx.x;   // packed col 0..4095
    const int c = p & 255, q = c & 63, wn = c >> 6, bx = p >> 8;
    const int orig = ((q >> 3) & 3) * Hh + bx * 64 + wn * 16 + ((q >> 5) << 3) + (q & 7);
    out[(size_t)k2 * 4 * Hh + p] =
        pack2(in[(size_t)(2 * k2) * 4 * Hh + orig], in[(size_t)(2 * k2 + 1) * 4 * Hh + orig]);
}

__global__ void cvt_half_kernel(const float* __restrict__ in, __half* __restrict__ out, size_t n)
{
    for (size_t i = (size_t)blockIdx.x * blockDim.x + threadIdx.x; i < n;
         i += (size_t)gridDim.x * blockDim.x)
        out[i] = __float2half(in[i]);
}

// ---------------- init ----------------
__global__ void init_state_kernel(const float* __restrict__ h0,
                                  const float* __restrict__ c0,
                                  const float* __restrict__ o0,
                                  const int* __restrict__ eos)
{
    int idx = blockIdx.x * blockDim.x + threadIdx.x;
    if (idx < Ll * Bsz * Hh) { g_h16a[idx] = __float2half(h0[idx]); g_c[idx] = c0[idx]; }
    if (idx < Bsz * Hh) g_out16[idx] = __float2half(o0[idx]);
    if (idx < Bsz) g_tok[idx] = eos[0];
}

// ---------------- pipelined fp16 GEMM ----------------
// Tile 64x256, 128 threads (4 warps each 64Mx64N), 3-stage cp.async, BK=32 halves.
// A: fp16 row-major (u32 = k-pair), lda in u32. B: pre-packed k-paired [K/2][N] u32.
// MODE 0: fp32 C (+bias). MODE 1: relu fp32 C. MODE 2: fused LSTM. MODE 3: fp16 C.
template <int MODE>
__global__ void __launch_bounds__(128) gemmh_kernel(
    const uint32_t* __restrict__ A, int ldaU, long zsA,
    const uint32_t* __restrict__ Bp, long zsB, int Nu,
    const float* __restrict__ bias,
    float* __restrict__ C, __half* __restrict__ Ch, int ldc, long zsC,
    int K,
    const float* __restrict__ rec,
    const float* __restrict__ bih, const float* __restrict__ bhh,
    float* __restrict__ cell, __half* __restrict__ hout, int last)
{
    extern __shared__ uint32_t smu[];
    A += blockIdx.z * zsA;
    Bp += blockIdx.z * zsB;
    if (MODE == 0 && C) C += blockIdx.z * zsC;
    const int tid = threadIdx.x;
    const int lane = tid & 31;
    const int w = tid >> 5;
    const int M0 = blockIdx.y * BM;
    const int bx = blockIdx.x;

    const uint32_t smb = (uint32_t)__cvta_generic_to_shared(smu);
    const int nch = K / BK;

    auto issue = [&](int c, int s) {
        uint32_t sa = smb + (uint32_t)s * (STAGEU * 4);
        uint32_t sb = sa + ASZU * 4;
        int k20 = c * KU;
#pragma unroll
        for (int i = 0; i < 2; i++) {
            int cid = tid + i * 128;
            int row = cid >> 2, kq = (cid & 3) << 2;
            cp16(sa + (uint32_t)(row * ASTU + kq) * 4,
                 A + (size_t)(M0 + row) * ldaU + k20 + kq);
        }
#pragma unroll
        for (int i = 0; i < 8; i++) {
            int cid = tid + i * 128;
            int kr = cid >> 6, nq = (cid & 63) << 2;
            cp16(sb + (uint32_t)(kr * BSTU + nq) * 4,
                 Bp + (size_t)(k20 + kr) * Nu + bx * BN + nq);
        }
        cpcommit();
    };

    float acc[4][8][4];
#pragma unroll
    for (int mt = 0; mt < 4; mt++)
#pragma unroll
        for (int t = 0; t < 8; t++)
#pragma unroll
            for (int j = 0; j < 4; j++) acc[mt][t][j] = 0.f;

    issue(0, 0);
    if (nch > 1) issue(1, 1);

    for (int c = 0; c < nch; c++) {
        cpwait<1>();
        __syncthreads();
        if (c + 2 < nch) issue(c + 2, (c + 2) % 3);

        const uint32_t* uA = smu + (c % 3) * STAGEU;
        const uint32_t* uB = uA + ASZU;
#pragma unroll
        for (int ks = 0; ks < 2; ks++) {
            uint32_t af[4][4];
            const int ac = ks * 8 + (lane & 3);
            const int ar = lane >> 2;
#pragma unroll
            for (int mt = 0; mt < 4; mt++) {
                const uint32_t* p = uA + (mt * 16 + ar) * ASTU + ac;
                af[mt][0] = p[0];
                af[mt][1] = p[8 * ASTU];
                af[mt][2] = p[4];
                af[mt][3] = p[8 * ASTU + 4];
            }
            uint32_t bf[8][2];
            const int bk = ks * 8 + (lane & 3);
            const int bn = w * 64 + (lane >> 2);
#pragma unroll
            for (int t = 0; t < 8; t++) {
                bf[t][0] = uB[bk * BSTU + bn + t * 8];
                bf[t][1] = uB[(bk + 4) * BSTU + bn + t * 8];
            }
#pragma unroll
            for (int mt = 0; mt < 4; mt++)
#pragma unroll
                for (int t = 0; t < 8; t++)
                    mma_f16(acc[mt][t], af[mt], bf[t]);
        }
        __syncthreads();
    }

    // ---------------- epilogue ----------------
    const int r0 = lane >> 2;
    const int cb = (lane & 3) * 2;
    if (MODE == 2) {
#pragma unroll
        for (int mt = 0; mt < 4; mt++)
#pragma unroll
            for (int tt = 0; tt < 2; tt++)
#pragma unroll
                for (int j = 0; j < 4; j++) {
                    int row = mt * 16 + r0 + (j >> 1) * 8;
                    int hid = bx * 64 + w * 16 + tt * 8 + cb + (j & 1);
                    int recb = row * (4 * Hh) + bx * 256 + w * 64 + tt * 32 + cb + (j & 1);
                    float xi = acc[mt][tt * 4 + 0][j] + rec[recb + 0]  + bih[hid]          + bhh[hid];
                    float xf = acc[mt][tt * 4 + 1][j] + rec[recb + 8]  + bih[Hh + hid]     + bhh[Hh + hid];
                    float xg = acc[mt][tt * 4 + 2][j] + rec[recb + 16] + bih[2 * Hh + hid] + bhh[2 * Hh + hid];
                    float xo = acc[mt][tt * 4 + 3][j] + rec[recb + 24] + bih[3 * Hh + hid] + bhh[3 * Hh + hid];
                    float iv = sigmoidf_(xi);
                    float fv = sigmoidf_(xf);
                    float gv = tanhf(xg);
                    float ov = sigmoidf_(xo);
                    size_t off = (size_t)row * Hh + hid;
                    float cn = fv * cell[off] + iv * gv;
                    float hn = ov * tanhf(cn);
                    cell[off] = cn;
                    hout[off] = __float2half(hn);
                    if (last) {
                        g_out16[off] = __float2half(hn);
                        g_xl16[(size_t)row * 3 * Hh + hid] = __float2half(hn);
                    }
                }
    } else {
#pragma unroll
        for (int mt = 0; mt < 4; mt++) {
            int ra = M0 + mt * 16 + r0;
#pragma unroll
            for (int t = 0; t < 8; t++) {
                int col = bx * BN + w * 64 + t * 8 + cb;
                float b0 = bias ? bias[col] : 0.f;
                float b1 = bias ? bias[col + 1] : 0.f;
                float v0 = acc[mt][t][0] + b0, v1 = acc[mt][t][1] + b1;
                float v2 = acc[mt][t][2] + b0, v3 = acc[mt][t][3] + b1;
                if (MODE == 1) {
                    v0 = fmaxf(v0, 0.f); v1 = fmaxf(v1, 0.f);
                    v2 = fmaxf(v2, 0.f); v3 = fmaxf(v3, 0.f);
                }
                if (MODE == 3) {
                    __half2* d0 = (__half2*)&Ch[(size_t)ra * ldc + col];
                    __half2* d1 = (__half2*)&Ch[(size_t)(ra + 8) * ldc + col];
                    *d0 = __floats2half2_rn(v0, v1);
                    *d1 = __floats2half2_rn(v2, v3);
                } else {
                    *(float2*)&C[(size_t)ra * ldc + col] = make_float2(v0, v1);
                    *(float2*)&C[(size_t)(ra + 8) * ldc + col] = make_float2(v2, v3);
                }
            }
        }
    }
}

// ---------------- attention scores ----------------
__global__ __launch_bounds__(128) void attn_scores_kernel(
    const float* __restrict__ is_on,
    const float* __restrict__ A2, const float* __restrict__ b2)
{
    const int t = blockIdx.x, b = blockIdx.y;
    const int tid = threadIdx.x;
    const __half2* ep = (const __half2*)(g_encproj16 + ((size_t)t * Bsz + b) * Aa);
    float2 e0 = __half22float2(ep[2 * tid]);
    float2 e1 = __half22float2(ep[2 * tid + 1]);
    const float4 d = ((const float4*)(g_dec + b * Aa))[tid];
    const float4 a = ((const float4*)A2)[tid];
    float s = tanhf(e0.x + d.x) * a.x + tanhf(e0.y + d.y) * a.y +
              tanhf(e1.x + d.z) * a.z + tanhf(e1.y + d.w) * a.w;
#pragma unroll
    for (int o = 16; o > 0; o >>= 1) s += __shfl_down_sync(0xffffffffu, s, o);
    __shared__ float ws[4];
    if ((tid & 31) == 0) ws[tid >> 5] = s;
    __syncthreads();
    if (tid == 0) {
        float tot = ws[0] + ws[1] + ws[2] + ws[3];
        g_scores[t * Bsz + b] = tot + b2[0] + (1.f - is_on[t * Bsz + b]) * (-1e30f);
    }
}

// ---------------- softmax over T + context (fp16 enc) ----------------
__global__ __launch_bounds__(256) void attn_context_kernel()
{
    const int b = blockIdx.x;
    const int dchunk = blockIdx.y;
    const int tid = threadIdx.x;
    __shared__ float sAlpha[TIN];
    __shared__ float red[256];

    float v = (tid < TIN) ? g_scores[tid * Bsz + b] : -3.4e38f;
    red[tid] = v;
    __syncthreads();
    for (int st = 128; st > 0; st >>= 1) {
        if (tid < st) red[tid] = fmaxf(red[tid], red[tid + st]);
        __syncthreads();
    }
    float mx = red[0];
    __syncthreads();
    float e = (tid < TIN) ? expf(v - mx) : 0.f;
    if (tid < TIN) sAlpha[tid] = e;
    red[tid] = e;
    __syncthreads();
    for (int st = 128; st > 0; st >>= 1) {
        if (tid < st) red[tid] += red[tid + st];
        __syncthreads();
    }
    float inv = 1.f / red[0];

    const int d = dchunk * 256 + tid;
    const __half* ep = g_enc16 + (size_t)b * (2 * Hh) + d;
    float acc = 0.f;
#pragma unroll 4
    for (int t = 0; t < TIN; t++)
        acc += sAlpha[t] * __half2float(ep[(size_t)t * Bsz * 2 * Hh]);
    __half ctx = __float2half(acc * inv);
    g_x016[b * (2 * Hh + Ee) + d] = ctx;
    g_xl16[b * 3 * Hh + Hh + d] = ctx;
}

// ---------------- embedding gather ----------------
__global__ void gather_emb_kernel()
{
    const int b = blockIdx.x;
    const int e = blockIdx.y * 256 + threadIdx.x;
    g_x016[b * (2 * Hh + Ee) + 2 * Hh + e] = g_emb16[(size_t)g_tok[b] * Ee + e];
}

// ---------------- softmax over V, 4-phase ----------------
__global__ __launch_bounds__(256) void smax_seg_kernel()
{
    const int b = blockIdx.x, s = blockIdx.y;
    const float* lr = g_logits + (size_t)b * Vv + s * SEGV;
    const int tid = threadIdx.x;
    __shared__ float rv[256];
    __shared__ int ri[256];
    float m = -3.4e38f;
    int mi = 0;
    for (int i = tid; i < SEGV; i += 256) {
        float x = lr[i];
        if (x > m) { m = x; mi = s * SEGV + i; }
    }
    rv[tid] = m; ri[tid] = mi;
    __syncthreads();
    for (int st = 128; st > 0; st >>= 1) {
        if (tid < st) {
            float vo = rv[tid + st]; int io = ri[tid + st];
            if (vo > rv[tid] || (vo == rv[tid] && io < ri[tid])) { rv[tid] = vo; ri[tid] = io; }
        }
        __syncthreads();
    }
    if (tid == 0) { g_pmax[b * NSEG + s] = rv[0]; g_pidx[b * NSEG + s] = ri[0]; }
}

__global__ void smax_tok_kernel()
{
    const int b = blockIdx.x;
    if (threadIdx.x == 0) {
        float m = g_pmax[b * NSEG];
        int mi = g_pidx[b * NSEG];
        for (int s = 1; s < NSEG; s++) {
            float v = g_pmax[b * NSEG + s];
            int i = g_pidx[b * NSEG + s];
            if (v > m || (v == m && i < mi)) { m = v; mi = i; }
        }
        g_tok[b] = mi;
    }
}

__global__ __launch_bounds__(256) void smax_exp_kernel(float* __restrict__ outp)
{
    const int b = blockIdx.x, s = blockIdx.y;
    const int tid = threadIdx.x;
    float gm = g_pmax[b * NSEG];
#pragma unroll
    for (int k = 1; k < NSEG; k++) gm = fmaxf(gm, g_pmax[b * NSEG + k]);
    const float4* lr4 = (const float4*)(g_logits + (size_t)b * Vv + s * SEGV);
    float4* o4 = (float4*)(outp + (size_t)b * Vv + s * SEGV);
    float sum = 0.f;
    for (int i = tid; i < SEGV / 4; i += 256) {
        float4 x = lr4[i];
        float4 e = make_float4(expf(x.x - gm), expf(x.y - gm), expf(x.z - gm), expf(x.w - gm));
        o4[i] = e;
        sum += e.x + e.y + e.z + e.w;
    }
    __shared__ float rv[256];
    rv[tid] = sum;
    __syncthreads();
    for (int st = 128; st > 0; st >>= 1) {
        if (tid < st) rv[tid] += rv[tid + st];
        __syncthreads();
    }
    if (tid == 0) g_psum[b * NSEG + s] = rv[0];
}

__global__ __launch_bounds__(256) void smax_scale_kernel(float* __restrict__ outp)
{
    const int b = blockIdx.x, s = blockIdx.y;
    const int tid = threadIdx.x;
    float tot = 0.f;
#pragma unroll
    for (int k = 0; k < NSEG; k++) tot += g_psum[b * NSEG + k];
    const float inv = 1.f / tot;
    float4* o4 = (float4*)(outp + (size_t)b * Vv + s * SEGV);
    for (int i = tid; i < SEGV / 4; i += 256) {
        float4 e = o4[i];
        o4[i] = make_float4(e.x * inv, e.y * inv, e.z * inv, e.w * inv);
    }
}

// ---------------- host orchestration ----------------
extern "C" void kernel_launch(void* const* d_in, const int* in_sizes, int n_in,
                              void* d_out, int out_size)
{
    const float* enc   = (const float*)d_in[0];
    const float* is_on = (const float*)d_in[1];
    const float* emb   = (const float*)d_in[2];
    const float* A1    = (const float*)d_in[3];
    const float* b1    = (const float*)d_in[4];
    const float* A2    = (const float*)d_in[5];
    const float* b2    = (const float*)d_in[6];
    const float* W_ih0 = (const float*)d_in[7];
    const float* W_ihr = (const float*)d_in[8];
    const float* W_hh  = (const float*)d_in[9];
    const float* b_ih  = (const float*)d_in[10];
    const float* b_hh  = (const float*)d_in[11];
    const float* Wl    = (const float*)d_in[12];
    const float* bl    = (const float*)d_in[13];
    const float* h0    = (const float*)d_in[14];
    const float* c0    = (const float*)d_in[15];
    const float* o0    = (const float*)d_in[16];
    const int*   eos   = (const int*)d_in[17];
    float* out = (float*)d_out;

    uint32_t *pWl, *pWih0, *pWihr, *pWhh, *pA1lo, *pA1hi;
    __half *pEmb16, *pEnc16, *pEncproj16, *pX016, *pXl16, *pHa, *pHb, *pOut16;
    float *pDec, *pC, *pRec, *pLogits;
    cudaGetSymbolAddress((void**)&pWl, g_Wl16);
    cudaGetSymbolAddress((void**)&pWih0, g_Wih016);
    cudaGetSymbolAddress((void**)&pWihr, g_Wihr16);
    cudaGetSymbolAddress((void**)&pWhh, g_Whh16);
    cudaGetSymbolAddress((void**)&pA1lo, g_A1lo16);
    cudaGetSymbolAddress((void**)&pA1hi, g_A1hi16);
    cudaGetSymbolAddress((void**)&pEmb16, g_emb16);
    cudaGetSymbolAddress((void**)&pEnc16, g_enc16);
    cudaGetSymbolAddress((void**)&pEncproj16, g_encproj16);
    cudaGetSymbolAddress((void**)&pX016, g_x016);
    cudaGetSymbolAddress((void**)&pXl16, g_xl16);
    cudaGetSymbolAddress((void**)&pHa, g_h16a);
    cudaGetSymbolAddress((void**)&pHb, g_h16b);
    cudaGetSymbolAddress((void**)&pOut16, g_out16);
    cudaGetSymbolAddress((void**)&pDec, g_dec);
    cudaGetSymbolAddress((void**)&pC, g_c);
    cudaGetSymbolAddress((void**)&pRec, g_rec);
    cudaGetSymbolAddress((void**)&pLogits, g_logits);

    cudaFuncSetAttribute(gemmh_kernel<0>, cudaFuncAttributeMaxDynamicSharedMemorySize, SMEMB);
    cudaFuncSetAttribute(gemmh_kernel<1>, cudaFuncAttributeMaxDynamicSharedMemorySize, SMEMB);
    cudaFuncSetAttribute(gemmh_kernel<2>, cudaFuncAttributeMaxDynamicSharedMemorySize, SMEMB);
    cudaFuncSetAttribute(gemmh_kernel<3>, cudaFuncAttributeMaxDynamicSharedMemorySize, SMEMB);

    // ---- per-launch weight packing / conversion ----
    pack_plain_kernel<<<dim3(Vv / 256, 3 * Hh / 2), 256>>>(Wl, pWl, Vv);
    pack_plain_kernel<<<dim3(2, Hh / 2), 256>>>(A1, pA1lo, Aa);
    pack_plain_kernel<<<dim3(2, Hh), 256>>>(A1 + (size_t)Hh * Aa, pA1hi, Aa);
    pack_gated_kernel<<<dim3(16, (2 * Hh + Ee) / 2, 1), 256>>>(W_ih0, pWih0, 0, 0);
    pack_gated_kernel<<<dim3(16, Hh / 2, 3), 256>>>(W_ihr, pWihr,
        (long)Hh * 4 * Hh, (long)(Hh / 2) * 4 * Hh);
    pack_gated_kernel<<<dim3(16, Hh / 2, Ll), 256>>>(W_hh, pWhh,
        (long)Hh * 4 * Hh, (long)(Hh / 2) * 4 * Hh);
    cvt_half_kernel<<<4096, 256>>>(emb, pEmb16, (size_t)Vv * Ee);
    cvt_half_kernel<<<4096, 256>>>(enc, pEnc16, (size_t)TIN * Bsz * 2 * Hh);

    init_state_kernel<<<(Ll * Bsz * Hh + 255) / 256, 256>>>(h0, c0, o0, eos);

    // enc_proj = enc @ A1[H:]  (8192x512, K=2048) -> fp16
    gemmh_kernel<3><<<dim3(2, 128), 128, SMEMB>>>(
        (const uint32_t*)pEnc16, Hh, 0, pA1hi, 0, Aa,
        nullptr, nullptr, pEncproj16, Aa, 0, 2 * Hh,
        nullptr, nullptr, nullptr, nullptr, nullptr, 0);

    for (int s = 0; s < TOUT; s++) {
        __half* hold = (s & 1) ? pHb : pHa;
        __half* hnew = (s & 1) ? pHa : pHb;

        // dec = out_prev @ A1[:H] + b1  (64x512, K=1024)
        gemmh_kernel<0><<<dim3(2, 1), 128, SMEMB>>>(
            (const uint32_t*)pOut16, Hh / 2, 0, pA1lo, 0, Aa,
            b1, pDec, nullptr, Aa, 0, Hh,
            nullptr, nullptr, nullptr, nullptr, nullptr, 0);

        attn_scores_kernel<<<dim3(TIN, Bsz), 128>>>(is_on, A2, b2);
        attn_context_kernel<<<dim3(Bsz, (2 * Hh) / 256), 256>>>();
        gather_emb_kernel<<<dim3(Bsz, Ee / 256), 256>>>();

        // recurrent partials, all layers batched: rec[l] = h_old[l] @ W_hh[l]
        gemmh_kernel<0><<<dim3(16, 1, Ll), 128, SMEMB>>>(
            (const uint32_t*)hold, Hh / 2, (long)Bsz * Hh / 2,
            pWhh, (long)(Hh / 2) * 4 * Hh, 4 * Hh,
            nullptr, pRec, nullptr, 4 * Hh, (long)Bsz * 4 * Hh, Hh,
            nullptr, nullptr, nullptr, nullptr, nullptr, 0);

        for (int l = 0; l < Ll; l++) {
            const __half* x = (l == 0) ? pX016 : (hnew + (size_t)(l - 1) * Bsz * Hh);
            int Kx = (l == 0) ? (2 * Hh + Ee) : Hh;
            const uint32_t* Wih = (l == 0) ? pWih0 : (pWihr + (size_t)(l - 1) * (Hh / 2) * 4 * Hh);
            gemmh_kernel<2><<<dim3(16, 1), 128, SMEMB>>>(
                (const uint32_t*)x, Kx / 2, 0, Wih, 0, 4 * Hh,
                nullptr, nullptr, nullptr, 0, 0, Kx,
                pRec + (size_t)l * Bsz * 4 * Hh,
                b_ih + (size_t)l * 4 * Hh, b_hh + (size_t)l * 4 * Hh,
                pC + (size_t)l * Bsz * Hh, hnew + (size_t)l * Bsz * Hh,
                (l == Ll - 1) ? 1 : 0);
        }

        // logits = relu([out|context] @ Wl + bl)  (64x32000, K=3072)
        gemmh_kernel<1><<<dim3(Vv / BN, 1), 128, SMEMB>>>(
            (const uint32_t*)pXl16, 3 * Hh / 2, 0, pWl, 0, Vv,
            bl, pLogits, nullptr, Vv, 0, 3 * Hh,
            nullptr, nullptr, nullptr, nullptr, nullptr, 0);

        smax_seg_kernel<<<dim3(Bsz, NSEG), 256>>>();
        smax_tok_kernel<<<Bsz, 32>>>();
        smax_exp_kernel<<<dim3(Bsz, NSEG), 256>>>(out + (size_t)s * Bsz * Vv);
        smax_scale_kernel<<<dim3(Bsz, NSEG), 256>>>(out + (size_t)s * Bsz * Vv);
    }
    (void)in_sizes; (void)n_in; (void)out_size;
}

// round 6
// speedup vs baseline: 7.3050x; 1.3246x over previous
#include <cuda_runtime.h>
#include <cuda_fp16.h>
#include <math.h>
#include <stdint.h>

#define Bsz 64
#define TIN 128
#define TOUT 32
#define Vv 32000
#define Ee 512
#define Hh 1024
#define Aa 512
#define Ll 4

// GEMM tiling (fp16, k-paired u32 domain)
#define BM 64
#define BK 32                   // halves per K-chunk
#define KU (BK / 2)             // 16 u32 rows per chunk
#define ASTU 20                 // A smem row stride (u32, pad 4)
#define ASZU (BM * ASTU)        // 1280 u32

// ---------------- fp16 packed weights (filled per launch) ----------------
__device__ __align__(16) uint32_t g_Wl16[(size_t)(3 * Hh / 2) * Vv];
__device__ __align__(16) uint32_t g_Wih016[(2 * Hh + Ee) / 2 * 4 * Hh];
__device__ __align__(16) uint32_t g_Wihr16[3][(Hh / 2) * 4 * Hh];
__device__ __align__(16) uint32_t g_Whh16[Ll][(Hh / 2) * 4 * Hh];
__device__ __align__(16) uint32_t g_A1lo16[(Hh / 2) * Aa];
__device__ __align__(16) uint32_t g_A1hi16[Hh * Aa];
__device__ __align__(16) __half g_emb16[(size_t)Vv * Ee];
__device__ __align__(16) __half g_enc16[(size_t)TIN * Bsz * 2 * Hh];

// ---------------- scratch ----------------
__device__ __align__(16) __half g_encproj16[(size_t)TIN * Bsz * Aa];
__device__ __align__(16) float g_dec[Bsz * Aa];
__device__ __align__(16) float g_scores[TIN * Bsz];
__device__ __align__(16) __half g_x016[Bsz * (2 * Hh + Ee)];
__device__ __align__(16) __half g_xl16[Bsz * 3 * Hh];
__device__ __align__(16) __half g_h16a[Ll * Bsz * Hh];
__device__ __align__(16) __half g_h16b[Ll * Bsz * Hh];
__device__ __align__(16) float g_c[Ll * Bsz * Hh];
__device__ __align__(16) __half g_out16[Bsz * Hh];
__device__ __align__(16) float g_rec[Ll * Bsz * 4 * Hh];
__device__ __align__(16) float g_logits[(size_t)Bsz * Vv];
__device__ unsigned long long g_maxpack[Bsz];
__device__ int g_tok[Bsz];

// ---------------- helpers ----------------
__device__ __forceinline__ uint32_t pack2(float lo, float hi)
{
    __half2 h = __floats2half2_rn(lo, hi);
    return *(uint32_t*)&h;
}
__device__ __forceinline__ void cp16(uint32_t dst, const void* src)
{
    asm volatile("cp.async.cg.shared.global [%0], [%1], 16;\n" :: "r"(dst), "l"(src));
}
__device__ __forceinline__ void cpcommit() { asm volatile("cp.async.commit_group;\n"); }
template <int N>
__device__ __forceinline__ void cpwait() { asm volatile("cp.async.wait_group %0;\n" :: "n"(N)); }

__device__ __forceinline__ void mma_f16(float* c, const uint32_t* a, const uint32_t* b)
{
    asm volatile(
        "mma.sync.aligned.m16n8k16.row.col.f32.f16.f16.f32 "
        "{%0,%1,%2,%3}, {%4,%5,%6,%7}, {%8,%9}, {%0,%1,%2,%3};"
        : "+f"(c[0]), "+f"(c[1]), "+f"(c[2]), "+f"(c[3])
        : "r"(a[0]), "r"(a[1]), "r"(a[2]), "r"(a[3]), "r"(b[0]), "r"(b[1]));
}
__device__ __forceinline__ float sigmoidf_(float x) { return 1.f / (1.f + expf(-x)); }

// ---------------- weight packing ----------------
__global__ void pack_plain_kernel(const float* __restrict__ in, uint32_t* __restrict__ out, int N)
{
    const int k2 = blockIdx.y;
    const int n = blockIdx.x * 256 + threadIdx.x;
    if (n < N)
        out[(size_t)k2 * N + n] =
            pack2(in[(size_t)(2 * k2) * N + n], in[(size_t)(2 * k2 + 1) * N + n]);
}

// gated pack for the NT=4 GEMM layout:
// packed col p: bx=p>>7, c=p&127, w=c>>5, gate=(c>>3)&3, u=c&7
// original col = gate*Hh + bx*32 + w*8 + u
__global__ void pack_gated_kernel(const float* __restrict__ in, uint32_t* __restrict__ out,
                                  long inStride, long outStride)
{
    in += blockIdx.z * inStride;
    out += blockIdx.z * outStride;
    const int k2 = blockIdx.y;
    const int p = blockIdx.x * 256 + threadIdx.x;
    const int c = p & 127, bx = p >> 7;
    const int orig = ((c >> 3) & 3) * Hh + bx * 32 + ((c >> 5) << 3) + (c & 7);
    out[(size_t)k2 * 4 * Hh + p] =
        pack2(in[(size_t)(2 * k2) * 4 * Hh + orig], in[(size_t)(2 * k2 + 1) * 4 * Hh + orig]);
}

__global__ void cvt_half_kernel(const float* __restrict__ in, __half* __restrict__ out, size_t n)
{
    for (size_t i = (size_t)blockIdx.x * blockDim.x + threadIdx.x; i < n;
         i += (size_t)gridDim.x * blockDim.x)
        out[i] = __float2half(in[i]);
}

// ---------------- init ----------------
__global__ void init_state_kernel(const float* __restrict__ h0,
                                  const float* __restrict__ c0,
                                  const float* __restrict__ o0,
                                  const int* __restrict__ eos)
{
    int idx = blockIdx.x * blockDim.x + threadIdx.x;
    if (idx < Ll * Bsz * Hh) { g_h16a[idx] = __float2half(h0[idx]); g_c[idx] = c0[idx]; }
    if (idx < Bsz * Hh) g_out16[idx] = __float2half(o0[idx]);
    if (idx < Bsz) { g_tok[idx] = eos[0]; g_maxpack[idx] = 0ull; }
}

// ---------------- pipelined fp16 GEMM ----------------
// Tile 64 x (NT*32), 128 threads (4 warps, each 64M x NT*8 N), 3-stage cp.async.
// MODE 0: fp32 C (+bias). MODE 1: relu fp32 C + fused argmax atomics.
// MODE 2: fused LSTM cell (NT=4, gate-interleaved packing). MODE 3: fp16 C.
template <int MODE, int NT>
__global__ void __launch_bounds__(128) gemmh_kernel(
    const uint32_t* __restrict__ A, int ldaU, long zsA,
    const uint32_t* __restrict__ Bp, long zsB, int Nu,
    const float* __restrict__ bias,
    float* __restrict__ C, __half* __restrict__ Ch, int ldc, long zsC,
    int K,
    const float* __restrict__ rec,
    const float* __restrict__ bih, const float* __restrict__ bhh,
    float* __restrict__ cell, __half* __restrict__ hout, int last,
    unsigned long long* __restrict__ maxpack)
{
    constexpr int BNX = NT * 32;
    constexpr int BSTU = BNX + 8;
    constexpr int BSZU = KU * BSTU;
    constexpr int STAGEU = ASZU + BSZU;
    constexpr int CPR = BNX / 4;     // u32-quads per B row

    extern __shared__ uint32_t smu[];
    __shared__ unsigned long long s_max[64];

    A += blockIdx.z * zsA;
    Bp += blockIdx.z * zsB;
    if (MODE == 0 && C) C += blockIdx.z * zsC;
    const int tid = threadIdx.x;
    const int lane = tid & 31;
    const int w = tid >> 5;
    const int M0 = blockIdx.y * BM;
    const int bx = blockIdx.x;

    if (MODE == 1 && tid < 64) s_max[tid] = 0ull;

    const uint32_t smb = (uint32_t)__cvta_generic_to_shared(smu);
    const int nch = K / BK;

    auto issue = [&](int c, int s) {
        uint32_t sa = smb + (uint32_t)s * (STAGEU * 4);
        uint32_t sb = sa + ASZU * 4;
        int k20 = c * KU;
#pragma unroll
        for (int i = 0; i < 2; i++) {
            int cid = tid + i * 128;
            int row = cid >> 2, kq = (cid & 3) << 2;
            cp16(sa + (uint32_t)(row * ASTU + kq) * 4,
                 A + (size_t)(M0 + row) * ldaU + k20 + kq);
        }
#pragma unroll
        for (int i = 0; i < NT; i++) {
            int cid = tid + i * 128;
            int kr = cid / CPR, nq = (cid % CPR) << 2;
            cp16(sb + (uint32_t)(kr * BSTU + nq) * 4,
                 Bp + (size_t)(k20 + kr) * Nu + bx * BNX + nq);
        }
        cpcommit();
    };

    float acc[4][NT][4];
#pragma unroll
    for (int mt = 0; mt < 4; mt++)
#pragma unroll
        for (int t = 0; t < NT; t++)
#pragma unroll
            for (int j = 0; j < 4; j++) acc[mt][t][j] = 0.f;

    issue(0, 0);
    if (nch > 1) issue(1, 1);

    for (int c = 0; c < nch; c++) {
        cpwait<1>();
        __syncthreads();
        if (c + 2 < nch) issue(c + 2, (c + 2) % 3);

        const uint32_t* uA = smu + (c % 3) * STAGEU;
        const uint32_t* uB = uA + ASZU;
#pragma unroll
        for (int ks = 0; ks < 2; ks++) {
            uint32_t af[4][4];
            const int ac = ks * 8 + (lane & 3);
            const int ar = lane >> 2;
#pragma unroll
            for (int mt = 0; mt < 4; mt++) {
                const uint32_t* p = uA + (mt * 16 + ar) * ASTU + ac;
                af[mt][0] = p[0];
                af[mt][1] = p[8 * ASTU];
                af[mt][2] = p[4];
                af[mt][3] = p[8 * ASTU + 4];
            }
            uint32_t bf[NT][2];
            const int bk = ks * 8 + (lane & 3);
            const int bn = w * (NT * 8) + (lane >> 2);
#pragma unroll
            for (int t = 0; t < NT; t++) {
                bf[t][0] = uB[bk * BSTU + bn + t * 8];
                bf[t][1] = uB[(bk + 4) * BSTU + bn + t * 8];
            }
#pragma unroll
            for (int mt = 0; mt < 4; mt++)
#pragma unroll
                for (int t = 0; t < NT; t++)
                    mma_f16(acc[mt][t], af[mt], bf[t]);
        }
        __syncthreads();
    }

    // ---------------- epilogue ----------------
    const int r0 = lane >> 2;
    const int cb = (lane & 3) * 2;
    if (MODE == 2) {
        // NT==4: t index is the gate (i,f,g,o)
#pragma unroll
        for (int mt = 0; mt < 4; mt++)
#pragma unroll
            for (int j = 0; j < 4; j++) {
                int row = mt * 16 + r0 + (j >> 1) * 8;
                int u = cb + (j & 1);
                int hid = bx * 32 + w * 8 + u;
                int recb = row * (4 * Hh) + bx * 128 + w * 32 + u;
                float xi = acc[mt][0][j] + rec[recb + 0]  + bih[hid]          + bhh[hid];
                float xf = acc[mt][1][j] + rec[recb + 8]  + bih[Hh + hid]     + bhh[Hh + hid];
                float xg = acc[mt][2][j] + rec[recb + 16] + bih[2 * Hh + hid] + bhh[2 * Hh + hid];
                float xo = acc[mt][3][j] + rec[recb + 24] + bih[3 * Hh + hid] + bhh[3 * Hh + hid];
                float iv = sigmoidf_(xi);
                float fv = sigmoidf_(xf);
                float gv = tanhf(xg);
                float ov = sigmoidf_(xo);
                size_t off = (size_t)row * Hh + hid;
                float cn = fv * cell[off] + iv * gv;
                float hn = ov * tanhf(cn);
                cell[off] = cn;
                hout[off] = __float2half(hn);
                if (last) {
                    g_out16[off] = __float2half(hn);
                    g_xl16[(size_t)row * 3 * Hh + hid] = __float2half(hn);
                }
            }
    } else {
#pragma unroll
        for (int mt = 0; mt < 4; mt++) {
            int ra = M0 + mt * 16 + r0;
#pragma unroll
            for (int jr = 0; jr < 2; jr++) {
                unsigned long long best = 0ull;
#pragma unroll
                for (int t = 0; t < NT; t++) {
                    int col = bx * BNX + w * (NT * 8) + t * 8 + cb;
                    float b0 = bias ? bias[col] : 0.f;
                    float b1 = bias ? bias[col + 1] : 0.f;
                    float v0 = acc[mt][t][jr * 2 + 0] + b0;
                    float v1 = acc[mt][t][jr * 2 + 1] + b1;
                    if (MODE == 1) {
                        v0 = fmaxf(v0, 0.f);
                        v1 = fmaxf(v1, 0.f);
                        unsigned long long p0 =
                            ((unsigned long long)__float_as_uint(v0) << 32) | (uint32_t)(~col);
                        unsigned long long p1 =
                            ((unsigned long long)__float_as_uint(v1) << 32) | (uint32_t)(~(col + 1));
                        if (p0 > best) best = p0;
                        if (p1 > best) best = p1;
                    }
                    int row = ra + jr * 8;
                    if (MODE == 3) {
                        *(__half2*)&Ch[(size_t)row * ldc + col] = __floats2half2_rn(v0, v1);
                    } else {
                        *(float2*)&C[(size_t)row * ldc + col] = make_float2(v0, v1);
                    }
                }
                if (MODE == 1)
                    atomicMax(&s_max[ra + jr * 8], best);
            }
        }
        if (MODE == 1) {
            __syncthreads();
            if (tid < 64) atomicMax(&maxpack[tid], s_max[tid]);
        }
    }
}

// ---------------- attention scores ----------------
__global__ __launch_bounds__(128) void attn_scores_kernel(
    const float* __restrict__ is_on,
    const float* __restrict__ A2, const float* __restrict__ b2)
{
    const int t = blockIdx.x, b = blockIdx.y;
    const int tid = threadIdx.x;
    const __half2* ep = (const __half2*)(g_encproj16 + ((size_t)t * Bsz + b) * Aa);
    float2 e0 = __half22float2(ep[2 * tid]);
    float2 e1 = __half22float2(ep[2 * tid + 1]);
    const float4 d = ((const float4*)(g_dec + b * Aa))[tid];
    const float4 a = ((const float4*)A2)[tid];
    float s = tanhf(e0.x + d.x) * a.x + tanhf(e0.y + d.y) * a.y +
              tanhf(e1.x + d.z) * a.z + tanhf(e1.y + d.w) * a.w;
#pragma unroll
    for (int o = 16; o > 0; o >>= 1) s += __shfl_down_sync(0xffffffffu, s, o);
    __shared__ float ws[4];
    if ((tid & 31) == 0) ws[tid >> 5] = s;
    __syncthreads();
    if (tid == 0) {
        float tot = ws[0] + ws[1] + ws[2] + ws[3];
        g_scores[t * Bsz + b] = tot + b2[0] + (1.f - is_on[t * Bsz + b]) * (-1e30f);
    }
}

// ---------------- softmax over T + context ----------------
__global__ __launch_bounds__(256) void attn_context_kernel()
{
    const int b = blockIdx.x;
    const int dchunk = blockIdx.y;
    const int tid = threadIdx.x;
    __shared__ float sAlpha[TIN];
    __shared__ float red[256];

    float v = (tid < TIN) ? g_scores[tid * Bsz + b] : -3.4e38f;
    red[tid] = v;
    __syncthreads();
    for (int st = 128; st > 0; st >>= 1) {
        if (tid < st) red[tid] = fmaxf(red[tid], red[tid + st]);
        __syncthreads();
    }
    float mx = red[0];
    __syncthreads();
    float e = (tid < TIN) ? expf(v - mx) : 0.f;
    if (tid < TIN) sAlpha[tid] = e;
    red[tid] = e;
    __syncthreads();
    for (int st = 128; st > 0; st >>= 1) {
        if (tid < st) red[tid] += red[tid + st];
        __syncthreads();
    }
    float inv = 1.f / red[0];

    const int d = dchunk * 256 + tid;
    const __half* ep = g_enc16 + (size_t)b * (2 * Hh) + d;
    float acc = 0.f;
#pragma unroll 4
    for (int t = 0; t < TIN; t++)
        acc += sAlpha[t] * __half2float(ep[(size_t)t * Bsz * 2 * Hh]);
    __half ctx = __float2half(acc * inv);
    g_x016[b * (2 * Hh + Ee) + d] = ctx;
    g_xl16[b * 3 * Hh + Hh + d] = ctx;
}

// ---------------- fused softmax-V + token + emb gather ----------------
__global__ __launch_bounds__(1024) void smax_final_kernel(float* __restrict__ outp)
{
    const int b = blockIdx.x;
    const int tid = threadIdx.x;
    const float* lr = g_logits + (size_t)b * Vv;
    float* pr = outp + (size_t)b * Vv;

    unsigned long long pk = g_maxpack[b];
    float gmax = __uint_as_float((uint32_t)(pk >> 32));
    int tok = (int)(~(uint32_t)(pk & 0xFFFFFFFFull));
    __syncthreads();           // all reads of g_maxpack done before reset
    if (tid == 0) {
        g_tok[b] = tok;
        g_maxpack[b] = 0ull;
    }
    // embedding gather for next step
    if (tid < Ee)
        g_x016[b * (2 * Hh + Ee) + 2 * Hh + tid] = g_emb16[(size_t)tok * Ee + tid];

    // pass 1: exp + store unnormalized, accumulate sum
    float sum = 0.f;
    for (int i = tid; i < Vv; i += 1024) {
        float e = expf(lr[i] - gmax);
        pr[i] = e;
        sum += e;
    }
    __shared__ float rv[1024];
    rv[tid] = sum;
    __syncthreads();
    for (int st = 512; st > 0; st >>= 1) {
        if (tid < st) rv[tid] += rv[tid + st];
        __syncthreads();
    }
    float inv = 1.f / rv[0];
    // pass 2: rescale (L2-resident)
    for (int i = tid; i < Vv; i += 1024)
        pr[i] *= inv;
}

// ---------------- host orchestration ----------------
extern "C" void kernel_launch(void* const* d_in, const int* in_sizes, int n_in,
                              void* d_out, int out_size)
{
    const float* enc   = (const float*)d_in[0];
    const float* is_on = (const float*)d_in[1];
    const float* emb   = (const float*)d_in[2];
    const float* A1    = (const float*)d_in[3];
    const float* b1    = (const float*)d_in[4];
    const float* A2    = (const float*)d_in[5];
    const float* b2    = (const float*)d_in[6];
    const float* W_ih0 = (const float*)d_in[7];
    const float* W_ihr = (const float*)d_in[8];
    const float* W_hh  = (const float*)d_in[9];
    const float* b_ih  = (const float*)d_in[10];
    const float* b_hh  = (const float*)d_in[11];
    const float* Wl    = (const float*)d_in[12];
    const float* bl    = (const float*)d_in[13];
    const float* h0    = (const float*)d_in[14];
    const float* c0    = (const float*)d_in[15];
    const float* o0    = (const float*)d_in[16];
    const int*   eos   = (const int*)d_in[17];
    float* out = (float*)d_out;

    uint32_t *pWl, *pWih0, *pWihr, *pWhh, *pA1lo, *pA1hi;
    __half *pEmb16, *pEnc16, *pEncproj16, *pX016, *pXl16, *pHa, *pHb, *pOut16;
    float *pDec, *pC, *pRec, *pLogits;
    unsigned long long* pMaxpack;
    cudaGetSymbolAddress((void**)&pWl, g_Wl16);
    cudaGetSymbolAddress((void**)&pWih0, g_Wih016);
    cudaGetSymbolAddress((void**)&pWihr, g_Wihr16);
    cudaGetSymbolAddress((void**)&pWhh, g_Whh16);
    cudaGetSymbolAddress((void**)&pA1lo, g_A1lo16);
    cudaGetSymbolAddress((void**)&pA1hi, g_A1hi16);
    cudaGetSymbolAddress((void**)&pEmb16, g_emb16);
    cudaGetSymbolAddress((void**)&pEnc16, g_enc16);
    cudaGetSymbolAddress((void**)&pEncproj16, g_encproj16);
    cudaGetSymbolAddress((void**)&pX016, g_x016);
    cudaGetSymbolAddress((void**)&pXl16, g_xl16);
    cudaGetSymbolAddress((void**)&pHa, g_h16a);
    cudaGetSymbolAddress((void**)&pHb, g_h16b);
    cudaGetSymbolAddress((void**)&pOut16, g_out16);
    cudaGetSymbolAddress((void**)&pDec, g_dec);
    cudaGetSymbolAddress((void**)&pC, g_c);
    cudaGetSymbolAddress((void**)&pRec, g_rec);
    cudaGetSymbolAddress((void**)&pLogits, g_logits);
    cudaGetSymbolAddress((void**)&pMaxpack, g_maxpack);

    // smem sizes: NT4 stage 3456 u32, NT8 stage 5504 u32, x4 bytes x3 stages
    const int SM4 = (ASZU + KU * (128 + 8)) * 4 * 3;
    const int SM8 = (ASZU + KU * (256 + 8)) * 4 * 3;
    cudaFuncSetAttribute(gemmh_kernel<3, 8>, cudaFuncAttributeMaxDynamicSharedMemorySize, SM8);
    cudaFuncSetAttribute(gemmh_kernel<1, 8>, cudaFuncAttributeMaxDynamicSharedMemorySize, SM8);
    cudaFuncSetAttribute(gemmh_kernel<0, 4>, cudaFuncAttributeMaxDynamicSharedMemorySize, SM4);
    cudaFuncSetAttribute(gemmh_kernel<2, 4>, cudaFuncAttributeMaxDynamicSharedMemorySize, SM4);

    // ---- per-launch weight packing ----
    pack_plain_kernel<<<dim3(Vv / 256, 3 * Hh / 2), 256>>>(Wl, pWl, Vv);
    pack_plain_kernel<<<dim3(2, Hh / 2), 256>>>(A1, pA1lo, Aa);
    pack_plain_kernel<<<dim3(2, Hh), 256>>>(A1 + (size_t)Hh * Aa, pA1hi, Aa);
    pack_gated_kernel<<<dim3(16, (2 * Hh + Ee) / 2, 1), 256>>>(W_ih0, pWih0, 0, 0);
    pack_gated_kernel<<<dim3(16, Hh / 2, 3), 256>>>(W_ihr, pWihr,
        (long)Hh * 4 * Hh, (long)(Hh / 2) * 4 * Hh);
    pack_gated_kernel<<<dim3(16, Hh / 2, Ll), 256>>>(W_hh, pWhh,
        (long)Hh * 4 * Hh, (long)(Hh / 2) * 4 * Hh);
    cvt_half_kernel<<<4096, 256>>>(emb, pEmb16, (size_t)Vv * Ee);
    cvt_half_kernel<<<4096, 256>>>(enc, pEnc16, (size_t)TIN * Bsz * 2 * Hh);

    init_state_kernel<<<(Ll * Bsz * Hh + 255) / 256, 256>>>(h0, c0, o0, eos);

    // enc_proj = enc @ A1[H:]  (8192x512, K=2048) -> fp16
    gemmh_kernel<3, 8><<<dim3(2, 128), 128, SM8>>>(
        (const uint32_t*)pEnc16, Hh, 0, pA1hi, 0, Aa,
        nullptr, nullptr, pEncproj16, Aa, 0, 2 * Hh,
        nullptr, nullptr, nullptr, nullptr, nullptr, 0, nullptr);

    for (int s = 0; s < TOUT; s++) {
        __half* hold = (s & 1) ? pHb : pHa;
        __half* hnew = (s & 1) ? pHa : pHb;

        // dec = out_prev @ A1[:H] + b1  (64x512, K=1024)
        gemmh_kernel<0, 4><<<dim3(4, 1), 128, SM4>>>(
            (const uint32_t*)pOut16, Hh / 2, 0, pA1lo, 0, Aa,
            b1, pDec, nullptr, Aa, 0, Hh,
            nullptr, nullptr, nullptr, nullptr, nullptr, 0, nullptr);

        attn_scores_kernel<<<dim3(TIN, Bsz), 128>>>(is_on, A2, b2);
        attn_context_kernel<<<dim3(Bsz, (2 * Hh) / 256), 256>>>();

        // recurrent partials, all layers batched: rec[l] = h_old[l] @ W_hh[l]
        gemmh_kernel<0, 4><<<dim3(32, 1, Ll), 128, SM4>>>(
            (const uint32_t*)hold, Hh / 2, (long)Bsz * Hh / 2,
            pWhh, (long)(Hh / 2) * 4 * Hh, 4 * Hh,
            nullptr, pRec, nullptr, 4 * Hh, (long)Bsz * 4 * Hh, Hh,
            nullptr, nullptr, nullptr, nullptr, nullptr, 0, nullptr);

        for (int l = 0; l < Ll; l++) {
            const __half* x = (l == 0) ? pX016 : (hnew + (size_t)(l - 1) * Bsz * Hh);
            int Kx = (l == 0) ? (2 * Hh + Ee) : Hh;
            const uint32_t* Wih = (l == 0) ? pWih0 : (pWihr + (size_t)(l - 1) * (Hh / 2) * 4 * Hh);
            gemmh_kernel<2, 4><<<dim3(32, 1), 128, SM4>>>(
                (const uint32_t*)x, Kx / 2, 0, Wih, 0, 4 * Hh,
                nullptr, nullptr, nullptr, 0, 0, Kx,
                pRec + (size_t)l * Bsz * 4 * Hh,
                b_ih + (size_t)l * 4 * Hh, b_hh + (size_t)l * 4 * Hh,
                pC + (size_t)l * Bsz * Hh, hnew + (size_t)l * Bsz * Hh,
                (l == Ll - 1) ? 1 : 0, nullptr);
        }

        // logits = relu([out|context] @ Wl + bl) + fused argmax
        gemmh_kernel<1, 8><<<dim3(Vv / 256, 1), 128, SM8>>>(
            (const uint32_t*)pXl16, 3 * Hh / 2, 0, pWl, 0, Vv,
            bl, pLogits, nullptr, Vv, 0, 3 * Hh,
            nullptr, nullptr, nullptr, nullptr, nullptr, 0, pMaxpack);

        // fused softmax + token select + emb gather
        smax_final_kernel<<<Bsz, 1024>>>(out + (size_t)s * Bsz * Vv);
    }
    (void)in_sizes; (void)n_in; (void)out_size;
}